// round 3
// baseline (speedup 1.0000x reference)
#include <cuda_runtime.h>

#define NODES 100000
#define EDGES 1600000
#define C 128
#define BN_EPS 1e-5f

// ---------------- scratch (static device globals; no allocation) -------------
__device__ float g_h[(size_t)NODES * C];    // activations between layers
__device__ float g_hw[(size_t)NODES * C];   // h @ W
__device__ float g_agg[(size_t)NODES * C];  // aggregation accumulator
__device__ float g_deg[NODES];
__device__ float g_dinv[NODES];
__device__ float g_stats[2 * C];            // column sum, sumsq
__device__ float g_ss[2 * C];               // BN scale, shift
__device__ int   g_is64;                    // edge_index dtype flag

// ---------------- dtype detection --------------------------------------------
// int64 edge ids < 100000 => every odd int32 word is 0. int32 ids => odd words
// are node ids, OR over 256 of them is ~never 0.
__global__ void k_detect(const int* __restrict__ ei32) {
    __shared__ int acc;
    if (threadIdx.x == 0) acc = 0;
    __syncthreads();
    int v = ei32[2 * threadIdx.x + 1];
    if (v != 0) atomicOr(&acc, 1);
    __syncthreads();
    if (threadIdx.x == 0) g_is64 = (acc == 0) ? 1 : 0;
}

__device__ __forceinline__ int load_idx(const void* ei, long long pos) {
    if (g_is64) return (int)((const long long*)ei)[pos];
    return ((const int*)ei)[pos];
}

// ---------------- degree / dinv ----------------------------------------------
__global__ void k_zero_deg() {
    int i = blockIdx.x * blockDim.x + threadIdx.x;
    if (i < NODES) g_deg[i] = 0.0f;
}

__global__ void k_deg(const void* __restrict__ ei) {
    int e = blockIdx.x * blockDim.x + threadIdx.x;
    if (e < EDGES) {
        int d = load_idx(ei, (long long)EDGES + e);
        if (d >= 0 && d < NODES) atomicAdd(&g_deg[d], 1.0f);
    }
}

__global__ void k_dinv() {
    int i = blockIdx.x * blockDim.x + threadIdx.x;
    if (i < NODES) g_dinv[i] = rsqrtf(g_deg[i] + 1.0f);
}

// ---------------- GEMM: g_hw = h @ W  (M=NODES, K=N=128) ---------------------
__global__ void __launch_bounds__(256) k_gemm(const float* __restrict__ x,
                                              int use_x,
                                              const float* __restrict__ W) {
    __shared__ float Ws[C * C];
    for (int i = threadIdx.x; i < C * C; i += 256) Ws[i] = W[i];
    __syncthreads();

    const float* __restrict__ h = use_x ? x : (const float*)g_h;

    const int warp = threadIdx.x >> 5;
    const int lane = threadIdx.x & 31;
    const int c = lane * 4;

    for (int row = blockIdx.x * 8 + warp; row < NODES; row += gridDim.x * 8) {
        const float4* hr = (const float4*)(h + (size_t)row * C);
        float a0 = 0.f, a1 = 0.f, a2 = 0.f, a3 = 0.f;
#pragma unroll 4
        for (int k4 = 0; k4 < 32; k4++) {
            const float4 h4 = __ldg(hr + k4);
            float4 w;
            w = *(const float4*)(Ws + (k4 * 4 + 0) * C + c);
            a0 = fmaf(h4.x, w.x, a0); a1 = fmaf(h4.x, w.y, a1);
            a2 = fmaf(h4.x, w.z, a2); a3 = fmaf(h4.x, w.w, a3);
            w = *(const float4*)(Ws + (k4 * 4 + 1) * C + c);
            a0 = fmaf(h4.y, w.x, a0); a1 = fmaf(h4.y, w.y, a1);
            a2 = fmaf(h4.y, w.z, a2); a3 = fmaf(h4.y, w.w, a3);
            w = *(const float4*)(Ws + (k4 * 4 + 2) * C + c);
            a0 = fmaf(h4.z, w.x, a0); a1 = fmaf(h4.z, w.y, a1);
            a2 = fmaf(h4.z, w.z, a2); a3 = fmaf(h4.z, w.w, a3);
            w = *(const float4*)(Ws + (k4 * 4 + 3) * C + c);
            a0 = fmaf(h4.w, w.x, a0); a1 = fmaf(h4.w, w.y, a1);
            a2 = fmaf(h4.w, w.z, a2); a3 = fmaf(h4.w, w.w, a3);
        }
        *(float4*)(g_hw + (size_t)row * C + c) = make_float4(a0, a1, a2, a3);
    }
}

// ---------------- agg = hw * dinv^2 + b  (self-loop + bias; pre-seeds agg) ---
__global__ void k_init(const float* __restrict__ b) {
    int i = blockIdx.x * blockDim.x + threadIdx.x;  // over NODES*32 float4s
    if (i >= NODES * 32) return;
    int row = i >> 5, q = i & 31;
    float s = g_dinv[row];
    s *= s;
    float4 v = *((const float4*)g_hw + i);
    float4 bb = __ldg((const float4*)b + q);
    v.x = fmaf(v.x, s, bb.x);
    v.y = fmaf(v.y, s, bb.y);
    v.z = fmaf(v.z, s, bb.z);
    v.w = fmaf(v.w, s, bb.w);
    *((float4*)g_agg + i) = v;
}

// ---------------- edge scatter: warp per edge, 4 atomics per lane ------------
__global__ void __launch_bounds__(256) k_scatter(const void* __restrict__ ei) {
    int t = blockIdx.x * blockDim.x + threadIdx.x;
    int e = t >> 5;
    if (e >= EDGES) return;
    int lane = threadIdx.x & 31;
    int src = load_idx(ei, e);
    int dst = load_idx(ei, (long long)EDGES + e);
    if ((unsigned)src >= NODES || (unsigned)dst >= NODES) return;
    float norm = g_dinv[src] * g_dinv[dst];
    float4 v = *((const float4*)(g_hw + (size_t)src * C) + lane);
    float* a = g_agg + (size_t)dst * C + lane * 4;
    atomicAdd(a + 0, v.x * norm);
    atomicAdd(a + 1, v.y * norm);
    atomicAdd(a + 2, v.z * norm);
    atomicAdd(a + 3, v.w * norm);
}

// ---------------- BN stats ----------------------------------------------------
__global__ void k_zero_stats() {
    int i = threadIdx.x;
    if (i < 2 * C) g_stats[i] = 0.0f;
}

__global__ void __launch_bounds__(128) k_stats() {
    int c = threadIdx.x;  // blockDim = 128
    float s = 0.f, s2 = 0.f;
    for (int row = blockIdx.x; row < NODES; row += gridDim.x) {
        float v = g_agg[(size_t)row * C + c];
        s += v;
        s2 = fmaf(v, v, s2);
    }
    atomicAdd(&g_stats[c], s);
    atomicAdd(&g_stats[C + c], s2);
}

__global__ void k_bnfin(const float* __restrict__ gamma, const float* __restrict__ beta) {
    int c = threadIdx.x;
    if (c < C) {
        const float inv_n = 1.0f / (float)NODES;
        float mean = g_stats[c] * inv_n;
        float var = g_stats[C + c] * inv_n - mean * mean;
        float sc = gamma[c] * rsqrtf(var + BN_EPS);
        g_ss[c] = sc;
        g_ss[C + c] = fmaf(-mean, sc, beta[c]);
    }
}

// ---------------- normalize + ReLU -------------------------------------------
__global__ void k_norm(float* __restrict__ dout, int to_out) {
    int i = blockIdx.x * blockDim.x + threadIdx.x;  // over NODES*32 float4s
    if (i >= NODES * 32) return;
    float* __restrict__ dst = to_out ? dout : (float*)g_h;
    int q = i & 31;
    float4 v = *((const float4*)g_agg + i);
    float4 sc = *((const float4*)g_ss + q);
    float4 sh = *((const float4*)(g_ss + C) + q);
    v.x = fmaxf(fmaf(v.x, sc.x, sh.x), 0.f);
    v.y = fmaxf(fmaf(v.y, sc.y, sh.y), 0.f);
    v.z = fmaxf(fmaf(v.z, sc.z, sh.z), 0.f);
    v.w = fmaxf(fmaf(v.w, sc.w, sh.w), 0.f);
    *((float4*)dst + i) = v;
}

// ---------------- launch -------------------------------------------------------
extern "C" void kernel_launch(void* const* d_in, const int* in_sizes, int n_in,
                              void* d_out, int out_size) {
    const float* x = (const float*)d_in[0];
    const void* ei = d_in[1];
    const float* W[3]  = {(const float*)d_in[2],  (const float*)d_in[6],  (const float*)d_in[10]};
    const float* b[3]  = {(const float*)d_in[3],  (const float*)d_in[7],  (const float*)d_in[11]};
    const float* gm[3] = {(const float*)d_in[4],  (const float*)d_in[8],  (const float*)d_in[12]};
    const float* bt[3] = {(const float*)d_in[5],  (const float*)d_in[9],  (const float*)d_in[13]};

    const int vecN = NODES * 32;                 // float4 count per feature buf
    const int vblk = (vecN + 255) / 256;

    k_detect<<<1, 256>>>((const int*)ei);

    // degree + dinv (recomputed every call; deterministic)
    k_zero_deg<<<(NODES + 255) / 256, 256>>>();
    k_deg<<<(EDGES + 255) / 256, 256>>>(ei);
    k_dinv<<<(NODES + 255) / 256, 256>>>();

    for (int L = 0; L < 3; L++) {
        k_gemm<<<444, 256>>>(x, L == 0 ? 1 : 0, W[L]);
        k_init<<<vblk, 256>>>(b[L]);
        k_scatter<<<(EDGES * 32 + 255) / 256, 256>>>(ei);
        k_zero_stats<<<1, 256>>>();
        k_stats<<<512, 128>>>();
        k_bnfin<<<1, 128>>>(gm[L], bt[L]);
        k_norm<<<vblk, 256>>>((float*)d_out, L == 2 ? 1 : 0);
    }
}

// round 4
// speedup vs baseline: 1.9264x; 1.9264x over previous
#include <cuda_runtime.h>

#define NODES 100000
#define EDGES 1600000
#define C 128
#define BN_EPS 1e-5f

// ---------------- scratch (static device globals; no allocation) -------------
__device__ float g_h[(size_t)NODES * C];    // activations between layers
__device__ float g_hw[(size_t)NODES * C];   // h @ W
__device__ float g_agg[(size_t)NODES * C];  // aggregation accumulator
__device__ float g_deg[NODES];
__device__ float g_dinv[NODES];
__device__ float g_stats[2 * C];            // column sum, sumsq
__device__ float g_ss[2 * C];               // BN scale, shift
__device__ int   g_is64;                    // edge_index dtype flag

// ---------------- dtype detection --------------------------------------------
__global__ void k_detect(const int* __restrict__ ei32) {
    __shared__ int acc;
    if (threadIdx.x == 0) acc = 0;
    __syncthreads();
    int v = ei32[2 * threadIdx.x + 1];
    if (v != 0) atomicOr(&acc, 1);
    __syncthreads();
    if (threadIdx.x == 0) g_is64 = (acc == 0) ? 1 : 0;
}

__device__ __forceinline__ int load_idx(const void* ei, long long pos) {
    if (g_is64) return (int)((const long long*)ei)[pos];
    return ((const int*)ei)[pos];
}

// ---------------- degree / dinv ----------------------------------------------
__global__ void k_zero_deg() {
    int i = blockIdx.x * blockDim.x + threadIdx.x;
    if (i < NODES) g_deg[i] = 0.0f;
}

__global__ void k_deg(const void* __restrict__ ei) {
    int e = blockIdx.x * blockDim.x + threadIdx.x;
    if (e < EDGES) {
        int d = load_idx(ei, (long long)EDGES + e);
        if ((unsigned)d < NODES) atomicAdd(&g_deg[d], 1.0f);
    }
}

__global__ void k_dinv() {
    int i = blockIdx.x * blockDim.x + threadIdx.x;
    if (i < NODES) g_dinv[i] = rsqrtf(g_deg[i] + 1.0f);
}

// ---------------- GEMM: hw = h @ W ; agg = hw*dinv^2 + b (fused epilogue) ----
// 4 rows per warp: each Ws LDS.128 feeds 16 FMAs -> FFMA-bound, not crossbar.
__global__ void __launch_bounds__(256) k_gemm(const float* __restrict__ x,
                                              int use_x,
                                              const float* __restrict__ W,
                                              const float* __restrict__ b) {
    __shared__ float Ws[C * C];
    for (int i = threadIdx.x; i < C * C; i += 256) Ws[i] = W[i];
    __syncthreads();

    const float* __restrict__ h = use_x ? x : (const float*)g_h;

    const int warp = threadIdx.x >> 5;
    const int lane = threadIdx.x & 31;
    const int c = lane * 4;
    const float4 bb = __ldg((const float4*)b + lane);

    for (int r0 = (blockIdx.x * 8 + warp) * 4; r0 < NODES; r0 += gridDim.x * 32) {
        float acc[4][4];
#pragma unroll
        for (int r = 0; r < 4; r++)
#pragma unroll
            for (int j = 0; j < 4; j++) acc[r][j] = 0.f;

        const float4* hr0 = (const float4*)(h + (size_t)r0 * C);
#pragma unroll 2
        for (int k4 = 0; k4 < 32; k4++) {
            float4 h4[4];
#pragma unroll
            for (int r = 0; r < 4; r++) h4[r] = __ldg(hr0 + r * 32 + k4);
#pragma unroll
            for (int kk = 0; kk < 4; kk++) {
                const float4 w = *(const float4*)(Ws + (k4 * 4 + kk) * C + c);
#pragma unroll
                for (int r = 0; r < 4; r++) {
                    const float hv = (&h4[r].x)[kk];
                    acc[r][0] = fmaf(hv, w.x, acc[r][0]);
                    acc[r][1] = fmaf(hv, w.y, acc[r][1]);
                    acc[r][2] = fmaf(hv, w.z, acc[r][2]);
                    acc[r][3] = fmaf(hv, w.w, acc[r][3]);
                }
            }
        }
#pragma unroll
        for (int r = 0; r < 4; r++) {
            const int row = r0 + r;
            float s = g_dinv[row];
            s *= s;
            const float4 v = make_float4(acc[r][0], acc[r][1], acc[r][2], acc[r][3]);
            *(float4*)(g_hw + (size_t)row * C + c) = v;
            float4 a;
            a.x = fmaf(v.x, s, bb.x);
            a.y = fmaf(v.y, s, bb.y);
            a.z = fmaf(v.z, s, bb.z);
            a.w = fmaf(v.w, s, bb.w);
            *(float4*)(g_agg + (size_t)row * C + c) = a;
        }
    }
}

// ---------------- edge scatter: warp per edge, one red.v4 per lane -----------
__global__ void __launch_bounds__(256) k_scatter(const void* __restrict__ ei) {
    int t = blockIdx.x * blockDim.x + threadIdx.x;
    int e = t >> 5;
    if (e >= EDGES) return;
    int lane = threadIdx.x & 31;
    int src = load_idx(ei, e);
    int dst = load_idx(ei, (long long)EDGES + e);
    if ((unsigned)src >= NODES || (unsigned)dst >= NODES) return;
    float norm = g_dinv[src] * g_dinv[dst];
    float4 v = __ldg((const float4*)(g_hw + (size_t)src * C) + lane);
    float* a = g_agg + (size_t)dst * C + (size_t)lane * 4;
    asm volatile("red.global.add.v4.f32 [%0], {%1, %2, %3, %4};"
                 :: "l"(a), "f"(v.x * norm), "f"(v.y * norm),
                    "f"(v.z * norm), "f"(v.w * norm)
                 : "memory");
}

// ---------------- BN stats ----------------------------------------------------
__global__ void k_zero_stats() {
    int i = threadIdx.x;
    if (i < 2 * C) g_stats[i] = 0.0f;
}

__global__ void __launch_bounds__(128) k_stats() {
    int c = threadIdx.x;  // blockDim = 128
    float s = 0.f, s2 = 0.f;
    for (int row = blockIdx.x; row < NODES; row += gridDim.x) {
        float v = g_agg[(size_t)row * C + c];
        s += v;
        s2 = fmaf(v, v, s2);
    }
    atomicAdd(&g_stats[c], s);
    atomicAdd(&g_stats[C + c], s2);
}

__global__ void k_bnfin(const float* __restrict__ gamma, const float* __restrict__ beta) {
    int c = threadIdx.x;
    if (c < C) {
        const float inv_n = 1.0f / (float)NODES;
        float mean = g_stats[c] * inv_n;
        float var = g_stats[C + c] * inv_n - mean * mean;
        float sc = gamma[c] * rsqrtf(var + BN_EPS);
        g_ss[c] = sc;
        g_ss[C + c] = fmaf(-mean, sc, beta[c]);
    }
}

// ---------------- normalize + ReLU -------------------------------------------
__global__ void k_norm(float* __restrict__ dout, int to_out) {
    int i = blockIdx.x * blockDim.x + threadIdx.x;  // over NODES*32 float4s
    if (i >= NODES * 32) return;
    float* __restrict__ dst = to_out ? dout : (float*)g_h;
    int q = i & 31;
    float4 v = *((const float4*)g_agg + i);
    float4 sc = *((const float4*)g_ss + q);
    float4 sh = *((const float4*)(g_ss + C) + q);
    v.x = fmaxf(fmaf(v.x, sc.x, sh.x), 0.f);
    v.y = fmaxf(fmaf(v.y, sc.y, sh.y), 0.f);
    v.z = fmaxf(fmaf(v.z, sc.z, sh.z), 0.f);
    v.w = fmaxf(fmaf(v.w, sc.w, sh.w), 0.f);
    *((float4*)dst + i) = v;
}

// ---------------- launch -------------------------------------------------------
extern "C" void kernel_launch(void* const* d_in, const int* in_sizes, int n_in,
                              void* d_out, int out_size) {
    const float* x = (const float*)d_in[0];
    const void* ei = d_in[1];
    const float* W[3]  = {(const float*)d_in[2],  (const float*)d_in[6],  (const float*)d_in[10]};
    const float* b[3]  = {(const float*)d_in[3],  (const float*)d_in[7],  (const float*)d_in[11]};
    const float* gm[3] = {(const float*)d_in[4],  (const float*)d_in[8],  (const float*)d_in[12]};
    const float* bt[3] = {(const float*)d_in[5],  (const float*)d_in[9],  (const float*)d_in[13]};

    const int vecN = NODES * 32;                 // float4 count per feature buf
    const int vblk = (vecN + 255) / 256;

    k_detect<<<1, 256>>>((const int*)ei);

    k_zero_deg<<<(NODES + 255) / 256, 256>>>();
    k_deg<<<(EDGES + 255) / 256, 256>>>(ei);
    k_dinv<<<(NODES + 255) / 256, 256>>>();

    for (int L = 0; L < 3; L++) {
        k_gemm<<<444, 256>>>(x, L == 0 ? 1 : 0, W[L], b[L]);
        k_scatter<<<(EDGES * 32 + 255) / 256, 256>>>(ei);
        k_zero_stats<<<1, 256>>>();
        k_stats<<<512, 128>>>();
        k_bnfin<<<1, 128>>>(gm[L], bt[L]);
        k_norm<<<vblk, 256>>>((float*)d_out, L == 2 ? 1 : 0);
    }
}

// round 5
// speedup vs baseline: 3.3558x; 1.7420x over previous
#include <cuda_runtime.h>

#define NODES 100000
#define EDGES 1600000
#define C 128
#define BN_EPS 1e-5f
#define SCAN_BLK 512
#define NBLK1 ((NODES + SCAN_BLK - 1) / SCAN_BLK)   // 196

// ---------------- scratch (static device globals; no allocation) -------------
__device__ float g_h[(size_t)NODES * C];
__device__ float g_hw[(size_t)NODES * C];
__device__ float g_agg[(size_t)NODES * C];
__device__ float g_dinv[NODES];
__device__ int   g_ideg[NODES];
__device__ int   g_scan[NODES];
__device__ int   g_bsum[256];
__device__ int   g_off[NODES + 1];
__device__ int   g_cur[NODES];
__device__ int   g_esrc[EDGES];
__device__ float g_enorm[EDGES];
__device__ float g_stats[2 * C];
__device__ float g_ss[2 * C];
__device__ int   g_is64;

// ---------------- dtype detection --------------------------------------------
__global__ void k_detect(const int* __restrict__ ei32) {
    __shared__ int acc;
    if (threadIdx.x == 0) acc = 0;
    __syncthreads();
    int v = ei32[2 * threadIdx.x + 1];
    if (v != 0) atomicOr(&acc, 1);
    __syncthreads();
    if (threadIdx.x == 0) g_is64 = (acc == 0) ? 1 : 0;
}

__device__ __forceinline__ int load_idx(const void* ei, long long pos) {
    if (g_is64) return (int)((const long long*)ei)[pos];
    return ((const int*)ei)[pos];
}

// ---------------- degree / dinv ----------------------------------------------
__global__ void k_zero_deg() {
    int i = blockIdx.x * blockDim.x + threadIdx.x;
    if (i < NODES) g_ideg[i] = 0;
}

__global__ void k_deg(const void* __restrict__ ei) {
    int e = blockIdx.x * blockDim.x + threadIdx.x;
    if (e < EDGES) {
        int d = load_idx(ei, (long long)EDGES + e);
        if ((unsigned)d < NODES) atomicAdd(&g_ideg[d], 1);
    }
}

__global__ void k_dinv() {
    int i = blockIdx.x * blockDim.x + threadIdx.x;
    if (i < NODES) g_dinv[i] = rsqrtf((float)g_ideg[i] + 1.0f);
}

// ---------------- CSR build: 3-kernel scan + fill -----------------------------
__global__ void k_scan1() {
    __shared__ int s[SCAN_BLK];
    int tid = threadIdx.x;
    int i = blockIdx.x * SCAN_BLK + tid;
    s[tid] = (i < NODES) ? g_ideg[i] : 0;
    __syncthreads();
#pragma unroll
    for (int d = 1; d < SCAN_BLK; d <<= 1) {
        int t = (tid >= d) ? s[tid - d] : 0;
        __syncthreads();
        s[tid] += t;
        __syncthreads();
    }
    if (i < NODES) g_scan[i] = s[tid];
    if (tid == SCAN_BLK - 1) g_bsum[blockIdx.x] = s[tid];
}

__global__ void k_scan2() {
    __shared__ int s[256];
    int tid = threadIdx.x;
    s[tid] = (tid < NBLK1) ? g_bsum[tid] : 0;
    __syncthreads();
#pragma unroll
    for (int d = 1; d < 256; d <<= 1) {
        int t = (tid >= d) ? s[tid - d] : 0;
        __syncthreads();
        s[tid] += t;
        __syncthreads();
    }
    if (tid < NBLK1) g_bsum[tid] = s[tid];
}

__global__ void k_scan3() {
    int i = blockIdx.x * blockDim.x + threadIdx.x;
    if (i < NODES) {
        int blk = i / SCAN_BLK;
        int add = (blk > 0) ? g_bsum[blk - 1] : 0;
        g_off[i + 1] = g_scan[i] + add;
        g_cur[i] = 0;
        if (i == 0) g_off[0] = 0;
    }
}

__global__ void k_fill(const void* __restrict__ ei) {
    int e = blockIdx.x * blockDim.x + threadIdx.x;
    if (e >= EDGES) return;
    int src = load_idx(ei, e);
    int dst = load_idx(ei, (long long)EDGES + e);
    if ((unsigned)src >= NODES || (unsigned)dst >= NODES) return;
    int pos = g_off[dst] + atomicAdd(&g_cur[dst], 1);
    g_esrc[pos] = src;
    g_enorm[pos] = g_dinv[src] * g_dinv[dst];
}

// ---------------- GEMM: g_hw = h @ W (4 rows/warp) ----------------------------
__global__ void __launch_bounds__(256) k_gemm(const float* __restrict__ x,
                                              int use_x,
                                              const float* __restrict__ W) {
    __shared__ float Ws[C * C];
    for (int i = threadIdx.x; i < C * C; i += 256) Ws[i] = W[i];
    __syncthreads();

    const float* __restrict__ h = use_x ? x : (const float*)g_h;

    const int warp = threadIdx.x >> 5;
    const int lane = threadIdx.x & 31;
    const int c = lane * 4;

    for (int r0 = (blockIdx.x * 8 + warp) * 4; r0 < NODES; r0 += gridDim.x * 32) {
        float acc[4][4];
#pragma unroll
        for (int r = 0; r < 4; r++)
#pragma unroll
            for (int j = 0; j < 4; j++) acc[r][j] = 0.f;

        const float4* hr0 = (const float4*)(h + (size_t)r0 * C);
#pragma unroll 2
        for (int k4 = 0; k4 < 32; k4++) {
            float4 h4[4];
#pragma unroll
            for (int r = 0; r < 4; r++) h4[r] = __ldg(hr0 + r * 32 + k4);
#pragma unroll
            for (int kk = 0; kk < 4; kk++) {
                const float4 w = *(const float4*)(Ws + (k4 * 4 + kk) * C + c);
#pragma unroll
                for (int r = 0; r < 4; r++) {
                    const float hv = (&h4[r].x)[kk];
                    acc[r][0] = fmaf(hv, w.x, acc[r][0]);
                    acc[r][1] = fmaf(hv, w.y, acc[r][1]);
                    acc[r][2] = fmaf(hv, w.z, acc[r][2]);
                    acc[r][3] = fmaf(hv, w.w, acc[r][3]);
                }
            }
        }
#pragma unroll
        for (int r = 0; r < 4; r++) {
            *(float4*)(g_hw + (size_t)(r0 + r) * C + c) =
                make_float4(acc[r][0], acc[r][1], acc[r][2], acc[r][3]);
        }
    }
}

// ---------------- gather aggregate + self-loop + bias + fused BN stats -------
__global__ void __launch_bounds__(256) k_aggr(const float* __restrict__ b) {
    __shared__ float sm[2 * C];
    if (threadIdx.x < 2 * C) sm[threadIdx.x] = 0.f;
    __syncthreads();

    const int warp = threadIdx.x >> 5;
    const int lane = threadIdx.x & 31;
    const float4 bb = __ldg((const float4*)b + lane);

    float4 ts = make_float4(0.f, 0.f, 0.f, 0.f);
    float4 ts2 = make_float4(0.f, 0.f, 0.f, 0.f);

    for (int d = blockIdx.x * 8 + warp; d < NODES; d += gridDim.x * 8) {
        const int beg = g_off[d], end = g_off[d + 1];
        float s = g_dinv[d];
        s *= s;
        float4 acc = __ldg((const float4*)(g_hw + (size_t)d * C) + lane);
        acc.x = fmaf(acc.x, s, bb.x);
        acc.y = fmaf(acc.y, s, bb.y);
        acc.z = fmaf(acc.z, s, bb.z);
        acc.w = fmaf(acc.w, s, bb.w);

        int e = beg;
        for (; e + 4 <= end; e += 4) {
            const int s0 = g_esrc[e], s1 = g_esrc[e + 1], s2 = g_esrc[e + 2], s3 = g_esrc[e + 3];
            const float n0 = g_enorm[e], n1 = g_enorm[e + 1], n2 = g_enorm[e + 2], n3 = g_enorm[e + 3];
            const float4 v0 = __ldg((const float4*)(g_hw + (size_t)s0 * C) + lane);
            const float4 v1 = __ldg((const float4*)(g_hw + (size_t)s1 * C) + lane);
            const float4 v2 = __ldg((const float4*)(g_hw + (size_t)s2 * C) + lane);
            const float4 v3 = __ldg((const float4*)(g_hw + (size_t)s3 * C) + lane);
            acc.x = fmaf(v0.x, n0, acc.x); acc.y = fmaf(v0.y, n0, acc.y);
            acc.z = fmaf(v0.z, n0, acc.z); acc.w = fmaf(v0.w, n0, acc.w);
            acc.x = fmaf(v1.x, n1, acc.x); acc.y = fmaf(v1.y, n1, acc.y);
            acc.z = fmaf(v1.z, n1, acc.z); acc.w = fmaf(v1.w, n1, acc.w);
            acc.x = fmaf(v2.x, n2, acc.x); acc.y = fmaf(v2.y, n2, acc.y);
            acc.z = fmaf(v2.z, n2, acc.z); acc.w = fmaf(v2.w, n2, acc.w);
            acc.x = fmaf(v3.x, n3, acc.x); acc.y = fmaf(v3.y, n3, acc.y);
            acc.z = fmaf(v3.z, n3, acc.z); acc.w = fmaf(v3.w, n3, acc.w);
        }
        for (; e < end; e++) {
            const int s0 = g_esrc[e];
            const float n0 = g_enorm[e];
            const float4 v0 = __ldg((const float4*)(g_hw + (size_t)s0 * C) + lane);
            acc.x = fmaf(v0.x, n0, acc.x); acc.y = fmaf(v0.y, n0, acc.y);
            acc.z = fmaf(v0.z, n0, acc.z); acc.w = fmaf(v0.w, n0, acc.w);
        }

        *((float4*)(g_agg + (size_t)d * C) + lane) = acc;

        ts.x += acc.x; ts.y += acc.y; ts.z += acc.z; ts.w += acc.w;
        ts2.x = fmaf(acc.x, acc.x, ts2.x); ts2.y = fmaf(acc.y, acc.y, ts2.y);
        ts2.z = fmaf(acc.z, acc.z, ts2.z); ts2.w = fmaf(acc.w, acc.w, ts2.w);
    }

    const int c0 = lane * 4;
    atomicAdd(&sm[c0 + 0], ts.x);  atomicAdd(&sm[c0 + 1], ts.y);
    atomicAdd(&sm[c0 + 2], ts.z);  atomicAdd(&sm[c0 + 3], ts.w);
    atomicAdd(&sm[C + c0 + 0], ts2.x);  atomicAdd(&sm[C + c0 + 1], ts2.y);
    atomicAdd(&sm[C + c0 + 2], ts2.z);  atomicAdd(&sm[C + c0 + 3], ts2.w);
    __syncthreads();
    if (threadIdx.x < 2 * C) atomicAdd(&g_stats[threadIdx.x], sm[threadIdx.x]);
}

// ---------------- BN finalize --------------------------------------------------
__global__ void k_zero_stats() {
    int i = threadIdx.x;
    if (i < 2 * C) g_stats[i] = 0.0f;
}

__global__ void k_bnfin(const float* __restrict__ gamma, const float* __restrict__ beta) {
    int c = threadIdx.x;
    if (c < C) {
        const float inv_n = 1.0f / (float)NODES;
        float mean = g_stats[c] * inv_n;
        float var = g_stats[C + c] * inv_n - mean * mean;
        float sc = gamma[c] * rsqrtf(var + BN_EPS);
        g_ss[c] = sc;
        g_ss[C + c] = fmaf(-mean, sc, beta[c]);
    }
}

// ---------------- normalize + ReLU --------------------------------------------
__global__ void k_norm(float* __restrict__ dout, int to_out) {
    int i = blockIdx.x * blockDim.x + threadIdx.x;
    if (i >= NODES * 32) return;
    float* __restrict__ dst = to_out ? dout : (float*)g_h;
    int q = i & 31;
    float4 v = *((const float4*)g_agg + i);
    float4 sc = *((const float4*)g_ss + q);
    float4 sh = *((const float4*)(g_ss + C) + q);
    v.x = fmaxf(fmaf(v.x, sc.x, sh.x), 0.f);
    v.y = fmaxf(fmaf(v.y, sc.y, sh.y), 0.f);
    v.z = fmaxf(fmaf(v.z, sc.z, sh.z), 0.f);
    v.w = fmaxf(fmaf(v.w, sc.w, sh.w), 0.f);
    *((float4*)dst + i) = v;
}

// ---------------- launch --------------------------------------------------------
extern "C" void kernel_launch(void* const* d_in, const int* in_sizes, int n_in,
                              void* d_out, int out_size) {
    const float* x = (const float*)d_in[0];
    const void* ei = d_in[1];
    const float* W[3]  = {(const float*)d_in[2],  (const float*)d_in[6],  (const float*)d_in[10]};
    const float* b[3]  = {(const float*)d_in[3],  (const float*)d_in[7],  (const float*)d_in[11]};
    const float* gm[3] = {(const float*)d_in[4],  (const float*)d_in[8],  (const float*)d_in[12]};
    const float* bt[3] = {(const float*)d_in[5],  (const float*)d_in[9],  (const float*)d_in[13]};

    const int vecN = NODES * 32;
    const int vblk = (vecN + 255) / 256;

    k_detect<<<1, 256>>>((const int*)ei);

    // degree + dinv + CSR (once per call, reused by all 3 layers)
    k_zero_deg<<<(NODES + 255) / 256, 256>>>();
    k_deg<<<(EDGES + 255) / 256, 256>>>(ei);
    k_dinv<<<(NODES + 255) / 256, 256>>>();
    k_scan1<<<NBLK1, SCAN_BLK>>>();
    k_scan2<<<1, 256>>>();
    k_scan3<<<(NODES + 255) / 256, 256>>>();
    k_fill<<<(EDGES + 255) / 256, 256>>>(ei);

    for (int L = 0; L < 3; L++) {
        k_gemm<<<444, 256>>>(x, L == 0 ? 1 : 0, W[L]);
        k_zero_stats<<<1, 256>>>();
        k_aggr<<<592, 256>>>(b[L]);
        k_bnfin<<<1, 128>>>(gm[L], bt[L]);
        k_norm<<<vblk, 256>>>((float*)d_out, L == 2 ? 1 : 0);
    }
}

// round 7
// speedup vs baseline: 3.8437x; 1.1454x over previous
#include <cuda_runtime.h>
#include <cuda_bf16.h>
#include <cstdint>

#define NODES 100000
#define EDGES 1600000
#define C 128
#define BN_EPS 1e-5f
#define SCAN_BLK 512
#define NBLK1 ((NODES + SCAN_BLK - 1) / SCAN_BLK)

#define MTILE 128
#define NTILES ((NODES + MTILE - 1) / MTILE)   // 782

// smem word (uint32) layout: padded row stride 68 for conflict-free frag loads
#define ROWW 68
#define AS_HI 0
#define AS_LO (128 * ROWW)
#define WS_HI (2 * 128 * ROWW)
#define WS_LO (3 * 128 * ROWW)
#define SMEM_WORDS (4 * 128 * ROWW)           // 34816 words = 139264 B

// ---------------- scratch -----------------------------------------------------
__device__ float g_hw[(size_t)NODES * C];
__device__ float g_agg[(size_t)NODES * C];
__device__ float g_dinv[NODES];
__device__ int   g_ideg[NODES];
__device__ int   g_scan[NODES];
__device__ int   g_bsum[256];
__device__ int   g_off[NODES + 1];
__device__ int   g_cur[NODES];
__device__ int   g_esrc[EDGES];
__device__ float g_enorm[EDGES];
__device__ __align__(16) float g_stats[2 * C];
__device__ __align__(16) float g_ss[2 * C];
__device__ int   g_is64;

// ---------------- helpers ------------------------------------------------------
__device__ __forceinline__ void split2(float a, float b, uint32_t& hi, uint32_t& lo) {
    __nv_bfloat16 ah = __float2bfloat16(a);
    __nv_bfloat16 bh = __float2bfloat16(b);
    __nv_bfloat16 al = __float2bfloat16(a - __bfloat162float(ah));
    __nv_bfloat16 bl = __float2bfloat16(b - __bfloat162float(bh));
    hi = (uint32_t)__bfloat16_as_ushort(ah) | ((uint32_t)__bfloat16_as_ushort(bh) << 16);
    lo = (uint32_t)__bfloat16_as_ushort(al) | ((uint32_t)__bfloat16_as_ushort(bl) << 16);
}

__device__ __forceinline__ void mma_bf16(float* d, const uint32_t* a, const uint32_t* b) {
    asm volatile(
        "mma.sync.aligned.m16n8k16.row.col.f32.bf16.bf16.f32 "
        "{%0,%1,%2,%3}, {%4,%5,%6,%7}, {%8,%9}, {%0,%1,%2,%3};"
        : "+f"(d[0]), "+f"(d[1]), "+f"(d[2]), "+f"(d[3])
        : "r"(a[0]), "r"(a[1]), "r"(a[2]), "r"(a[3]), "r"(b[0]), "r"(b[1]));
}

// ---------------- dtype detection ----------------------------------------------
__global__ void k_detect(const int* __restrict__ ei32) {
    __shared__ int acc;
    if (threadIdx.x == 0) acc = 0;
    __syncthreads();
    int v = ei32[2 * threadIdx.x + 1];
    if (v != 0) atomicOr(&acc, 1);
    __syncthreads();
    if (threadIdx.x == 0) g_is64 = (acc == 0) ? 1 : 0;
}

__device__ __forceinline__ int load_idx(const void* ei, long long pos) {
    if (g_is64) return (int)((const long long*)ei)[pos];
    return ((const int*)ei)[pos];
}

// ---------------- degree / dinv / CSR -------------------------------------------
__global__ void k_zero_deg() {
    int i = blockIdx.x * blockDim.x + threadIdx.x;
    if (i < NODES) g_ideg[i] = 0;
}

__global__ void k_deg(const void* __restrict__ ei) {
    int e = blockIdx.x * blockDim.x + threadIdx.x;
    if (e < EDGES) {
        int d = load_idx(ei, (long long)EDGES + e);
        if ((unsigned)d < NODES) atomicAdd(&g_ideg[d], 1);
    }
}

__global__ void k_dinv() {
    int i = blockIdx.x * blockDim.x + threadIdx.x;
    if (i < NODES) g_dinv[i] = rsqrtf((float)g_ideg[i] + 1.0f);
}

__global__ void k_scan1() {
    __shared__ int s[SCAN_BLK];
    int tid = threadIdx.x;
    int i = blockIdx.x * SCAN_BLK + tid;
    s[tid] = (i < NODES) ? g_ideg[i] : 0;
    __syncthreads();
#pragma unroll
    for (int d = 1; d < SCAN_BLK; d <<= 1) {
        int t = (tid >= d) ? s[tid - d] : 0;
        __syncthreads();
        s[tid] += t;
        __syncthreads();
    }
    if (i < NODES) g_scan[i] = s[tid];
    if (tid == SCAN_BLK - 1) g_bsum[blockIdx.x] = s[tid];
}

__global__ void k_scan2() {
    __shared__ int s[256];
    int tid = threadIdx.x;
    s[tid] = (tid < NBLK1) ? g_bsum[tid] : 0;
    __syncthreads();
#pragma unroll
    for (int d = 1; d < 256; d <<= 1) {
        int t = (tid >= d) ? s[tid - d] : 0;
        __syncthreads();
        s[tid] += t;
        __syncthreads();
    }
    if (tid < NBLK1) g_bsum[tid] = s[tid];
}

__global__ void k_scan3() {
    int i = blockIdx.x * blockDim.x + threadIdx.x;
    if (i < NODES) {
        int blk = i / SCAN_BLK;
        int add = (blk > 0) ? g_bsum[blk - 1] : 0;
        g_off[i + 1] = g_scan[i] + add;
        g_cur[i] = 0;
        if (i == 0) g_off[0] = 0;
    }
}

__global__ void k_fill(const void* __restrict__ ei) {
    int e = blockIdx.x * blockDim.x + threadIdx.x;
    if (e >= EDGES) return;
    int src = load_idx(ei, e);
    int dst = load_idx(ei, (long long)EDGES + e);
    if ((unsigned)src >= NODES || (unsigned)dst >= NODES) return;
    int pos = g_off[dst] + atomicAdd(&g_cur[dst], 1);
    g_esrc[pos] = src;
    g_enorm[pos] = g_dinv[src] * g_dinv[dst];
}

// ---------------- mma.sync GEMM: g_hw = norm(h) @ W --------------------------------
// A = node-tile [128 x K128] row-major, B = W [K128 x N128] col-major (staged as W^T).
// bf16 hi/lo split, 3 passes, fp32 accum. layer>0: h = relu(g_agg*sc+sh) inline.
__global__ void __launch_bounds__(256, 1) k_gemm_mma(const float* __restrict__ x,
                                                     int use_x,
                                                     const float* __restrict__ W) {
    extern __shared__ __align__(16) uint32_t sw[];
    const int tid = threadIdx.x;
    const int wid = tid >> 5;
    const int lane = tid & 31;
    const int g = lane >> 2;      // group row/col
    const int tc = lane & 3;
    const int wm = wid & 1;       // 2 m-halves of 64
    const int wn = wid >> 1;      // 4 n-quarters of 32

    // ---- stage W^T hi/lo once: thread owns outcol n = tid&127, k-half tid>>7 ----
    {
        const int n = tid & 127;
        const int kh = tid >> 7;
#pragma unroll 8
        for (int k2 = 0; k2 < 32; k2++) {
            const int k = kh * 64 + k2 * 2;
            float w0 = __ldg(W + (size_t)k * C + n);
            float w1 = __ldg(W + (size_t)(k + 1) * C + n);
            uint32_t hp, lp;
            split2(w0, w1, hp, lp);
            sw[WS_HI + n * ROWW + kh * 32 + k2] = hp;
            sw[WS_LO + n * ROWW + kh * 32 + k2] = lp;
        }
    }

    const float* __restrict__ hsrc = use_x ? x : (const float*)g_agg;

    for (int tile = blockIdx.x; tile < NTILES; tile += gridDim.x) {
        const int base = tile * MTILE;
        const int rem = min(MTILE, NODES - base);

        __syncthreads();  // prior tile's frag loads done before restage

        // ---- stage A tile: 128 rows x 32 float4, coalesced; fused BN+ReLU ----
#pragma unroll
        for (int it = 0; it < 16; it++) {
            const int f = it * 256 + tid;
            const int row = f >> 5;
            const int q4 = f & 31;
            float4 v;
            if (row < rem) {
                v = __ldg((const float4*)(hsrc + (size_t)(base + row) * C) + q4);
                if (!use_x) {
                    const float4 sc = ((const float4*)g_ss)[q4];
                    const float4 sh = ((const float4*)g_ss)[32 + q4];
                    v.x = fmaxf(fmaf(v.x, sc.x, sh.x), 0.f);
                    v.y = fmaxf(fmaf(v.y, sc.y, sh.y), 0.f);
                    v.z = fmaxf(fmaf(v.z, sc.z, sh.z), 0.f);
                    v.w = fmaxf(fmaf(v.w, sc.w, sh.w), 0.f);
                }
            } else {
                v = make_float4(0.f, 0.f, 0.f, 0.f);
            }
            uint32_t h0, l0, h1, l1;
            split2(v.x, v.y, h0, l0);
            split2(v.z, v.w, h1, l1);
            const int p = row * ROWW + q4 * 2;
            sw[AS_HI + p] = h0;  sw[AS_HI + p + 1] = h1;
            sw[AS_LO + p] = l0;  sw[AS_LO + p + 1] = l1;
        }
        __syncthreads();

        // ---- mainloop: 8 k16-steps, warp tile 64x32 = 4m x 4n frags ----
        float acc[4][4][4];
#pragma unroll
        for (int mf = 0; mf < 4; mf++)
#pragma unroll
            for (int nf = 0; nf < 4; nf++)
#pragma unroll
                for (int j = 0; j < 4; j++) acc[mf][nf][j] = 0.f;

#pragma unroll
        for (int ks = 0; ks < 8; ks++) {
            uint32_t ah[4][4], al[4][4], bh[4][2], bl[4][2];
            const int cb = ks * 8 + tc;
#pragma unroll
            for (int mf = 0; mf < 4; mf++) {
                const int r = wm * 64 + mf * 16 + g;
                ah[mf][0] = sw[AS_HI + r * ROWW + cb];
                ah[mf][1] = sw[AS_HI + (r + 8) * ROWW + cb];
                ah[mf][2] = sw[AS_HI + r * ROWW + cb + 4];
                ah[mf][3] = sw[AS_HI + (r + 8) * ROWW + cb + 4];
                al[mf][0] = sw[AS_LO + r * ROWW + cb];
                al[mf][1] = sw[AS_LO + (r + 8) * ROWW + cb];
                al[mf][2] = sw[AS_LO + r * ROWW + cb + 4];
                al[mf][3] = sw[AS_LO + (r + 8) * ROWW + cb + 4];
            }
#pragma unroll
            for (int nf = 0; nf < 4; nf++) {
                const int n = wn * 32 + nf * 8 + g;
                bh[nf][0] = sw[WS_HI + n * ROWW + cb];
                bh[nf][1] = sw[WS_HI + n * ROWW + cb + 4];
                bl[nf][0] = sw[WS_LO + n * ROWW + cb];
                bl[nf][1] = sw[WS_LO + n * ROWW + cb + 4];
            }
#pragma unroll
            for (int mf = 0; mf < 4; mf++)
#pragma unroll
                for (int nf = 0; nf < 4; nf++) {
                    mma_bf16(acc[mf][nf], ah[mf], bh[nf]);
                    mma_bf16(acc[mf][nf], ah[mf], bl[nf]);
                    mma_bf16(acc[mf][nf], al[mf], bh[nf]);
                }
        }

        // ---- epilogue: D[m][n] -> g_hw[node][outcol] ----
#pragma unroll
        for (int mf = 0; mf < 4; mf++) {
            const int m0 = wm * 64 + mf * 16 + g;
#pragma unroll
            for (int nf = 0; nf < 4; nf++) {
                const int cc = wn * 32 + nf * 8 + tc * 2;
                if (m0 < rem) {
                    float2 v = make_float2(acc[mf][nf][0], acc[mf][nf][1]);
                    *(float2*)(g_hw + (size_t)(base + m0) * C + cc) = v;
                }
                if (m0 + 8 < rem) {
                    float2 v = make_float2(acc[mf][nf][2], acc[mf][nf][3]);
                    *(float2*)(g_hw + (size_t)(base + m0 + 8) * C + cc) = v;
                }
            }
        }
    }
}

// ---------------- gather aggregate + self-loop + bias + fused BN stats ----------
__global__ void __launch_bounds__(256) k_aggr(const float* __restrict__ b) {
    __shared__ float sm[2 * C];
    if (threadIdx.x < 2 * C) sm[threadIdx.x] = 0.f;
    __syncthreads();

    const int warp = threadIdx.x >> 5;
    const int lane = threadIdx.x & 31;
    const float4 bb = __ldg((const float4*)b + lane);

    float4 ts = make_float4(0.f, 0.f, 0.f, 0.f);
    float4 ts2 = make_float4(0.f, 0.f, 0.f, 0.f);

    for (int d = blockIdx.x * 8 + warp; d < NODES; d += gridDim.x * 8) {
        const int beg = g_off[d], end = g_off[d + 1];
        float s = g_dinv[d];
        s *= s;
        float4 acc = __ldg((const float4*)(g_hw + (size_t)d * C) + lane);
        acc.x = fmaf(acc.x, s, bb.x);
        acc.y = fmaf(acc.y, s, bb.y);
        acc.z = fmaf(acc.z, s, bb.z);
        acc.w = fmaf(acc.w, s, bb.w);

        int e = beg;
        for (; e + 4 <= end; e += 4) {
            const int s0 = g_esrc[e], s1 = g_esrc[e + 1], s2 = g_esrc[e + 2], s3 = g_esrc[e + 3];
            const float n0 = g_enorm[e], n1 = g_enorm[e + 1], n2 = g_enorm[e + 2], n3 = g_enorm[e + 3];
            const float4 v0 = __ldg((const float4*)(g_hw + (size_t)s0 * C) + lane);
            const float4 v1 = __ldg((const float4*)(g_hw + (size_t)s1 * C) + lane);
            const float4 v2 = __ldg((const float4*)(g_hw + (size_t)s2 * C) + lane);
            const float4 v3 = __ldg((const float4*)(g_hw + (size_t)s3 * C) + lane);
            acc.x = fmaf(v0.x, n0, acc.x); acc.y = fmaf(v0.y, n0, acc.y);
            acc.z = fmaf(v0.z, n0, acc.z); acc.w = fmaf(v0.w, n0, acc.w);
            acc.x = fmaf(v1.x, n1, acc.x); acc.y = fmaf(v1.y, n1, acc.y);
            acc.z = fmaf(v1.z, n1, acc.z); acc.w = fmaf(v1.w, n1, acc.w);
            acc.x = fmaf(v2.x, n2, acc.x); acc.y = fmaf(v2.y, n2, acc.y);
            acc.z = fmaf(v2.z, n2, acc.z); acc.w = fmaf(v2.w, n2, acc.w);
            acc.x = fmaf(v3.x, n3, acc.x); acc.y = fmaf(v3.y, n3, acc.y);
            acc.z = fmaf(v3.z, n3, acc.z); acc.w = fmaf(v3.w, n3, acc.w);
        }
        for (; e < end; e++) {
            const int s0 = g_esrc[e];
            const float n0 = g_enorm[e];
            const float4 v0 = __ldg((const float4*)(g_hw + (size_t)s0 * C) + lane);
            acc.x = fmaf(v0.x, n0, acc.x); acc.y = fmaf(v0.y, n0, acc.y);
            acc.z = fmaf(v0.z, n0, acc.z); acc.w = fmaf(v0.w, n0, acc.w);
        }

        *((float4*)(g_agg + (size_t)d * C) + lane) = acc;

        ts.x += acc.x; ts.y += acc.y; ts.z += acc.z; ts.w += acc.w;
        ts2.x = fmaf(acc.x, acc.x, ts2.x); ts2.y = fmaf(acc.y, acc.y, ts2.y);
        ts2.z = fmaf(acc.z, acc.z, ts2.z); ts2.w = fmaf(acc.w, acc.w, ts2.w);
    }

    const int c0 = lane * 4;
    atomicAdd(&sm[c0 + 0], ts.x);  atomicAdd(&sm[c0 + 1], ts.y);
    atomicAdd(&sm[c0 + 2], ts.z);  atomicAdd(&sm[c0 + 3], ts.w);
    atomicAdd(&sm[C + c0 + 0], ts2.x);  atomicAdd(&sm[C + c0 + 1], ts2.y);
    atomicAdd(&sm[C + c0 + 2], ts2.z);  atomicAdd(&sm[C + c0 + 3], ts2.w);
    __syncthreads();
    if (threadIdx.x < 2 * C) atomicAdd(&g_stats[threadIdx.x], sm[threadIdx.x]);
}

// ---------------- BN finalize ----------------------------------------------------
__global__ void k_zero_stats() {
    int i = threadIdx.x;
    if (i < 2 * C) g_stats[i] = 0.0f;
}

__global__ void k_bnfin(const float* __restrict__ gamma, const float* __restrict__ beta) {
    int c = threadIdx.x;
    if (c < C) {
        const float inv_n = 1.0f / (float)NODES;
        float mean = g_stats[c] * inv_n;
        float var = g_stats[C + c] * inv_n - mean * mean;
        float sc = gamma[c] * rsqrtf(var + BN_EPS);
        g_ss[c] = sc;
        g_ss[C + c] = fmaf(-mean, sc, beta[c]);
    }
}

// ---------------- final normalize + ReLU -> d_out --------------------------------
__global__ void k_norm(float* __restrict__ dout) {
    int i = blockIdx.x * blockDim.x + threadIdx.x;
    if (i >= NODES * 32) return;
    int q = i & 31;
    float4 v = *((const float4*)g_agg + i);
    float4 sc = *((const float4*)g_ss + q);
    float4 sh = *((const float4*)(g_ss + C) + q);
    v.x = fmaxf(fmaf(v.x, sc.x, sh.x), 0.f);
    v.y = fmaxf(fmaf(v.y, sc.y, sh.y), 0.f);
    v.z = fmaxf(fmaf(v.z, sc.z, sh.z), 0.f);
    v.w = fmaxf(fmaf(v.w, sc.w, sh.w), 0.f);
    *((float4*)dout + i) = v;
}

// ---------------- launch -----------------------------------------------------------
extern "C" void kernel_launch(void* const* d_in, const int* in_sizes, int n_in,
                              void* d_out, int out_size) {
    const float* x = (const float*)d_in[0];
    const void* ei = d_in[1];
    const float* W[3]  = {(const float*)d_in[2],  (const float*)d_in[6],  (const float*)d_in[10]};
    const float* b[3]  = {(const float*)d_in[3],  (const float*)d_in[7],  (const float*)d_in[11]};
    const float* gm[3] = {(const float*)d_in[4],  (const float*)d_in[8],  (const float*)d_in[12]};
    const float* bt[3] = {(const float*)d_in[5],  (const float*)d_in[9],  (const float*)d_in[13]};

    cudaFuncSetAttribute(k_gemm_mma, cudaFuncAttributeMaxDynamicSharedMemorySize,
                         SMEM_WORDS * 4);

    const int vblk = (NODES * 32 + 255) / 256;

    k_detect<<<1, 256>>>((const int*)ei);

    k_zero_deg<<<(NODES + 255) / 256, 256>>>();
    k_deg<<<(EDGES + 255) / 256, 256>>>(ei);
    k_dinv<<<(NODES + 255) / 256, 256>>>();
    k_scan1<<<NBLK1, SCAN_BLK>>>();
    k_scan2<<<1, 256>>>();
    k_scan3<<<(NODES + 255) / 256, 256>>>();
    k_fill<<<(EDGES + 255) / 256, 256>>>(ei);

    for (int L = 0; L < 3; L++) {
        k_gemm_mma<<<148, 256, SMEM_WORDS * 4>>>(x, L == 0 ? 1 : 0, W[L]);
        k_zero_stats<<<1, 256>>>();
        k_aggr<<<592, 256>>>(b[L]);
        k_bnfin<<<1, 128>>>(gm[L], bt[L]);
    }
    k_norm<<<vblk, 256>>>((float*)d_out);
}

// round 8
// speedup vs baseline: 4.4754x; 1.1643x over previous
#include <cuda_runtime.h>
#include <cuda_bf16.h>
#include <cstdint>

#define NODES 100000
#define EDGES 1600000
#define C 128
#define BN_EPS 1e-5f
#define SCAN_BLK 512
#define NBLK1 ((NODES + SCAN_BLK - 1) / SCAN_BLK)

#define MTILE 64
#define NTILES ((NODES + MTILE - 1) / MTILE)   // 1563

// smem word (uint32) layout: padded row stride 68 -> bank = 4g+tc, conflict-free
#define ROWW 68
#define AS_HI 0
#define AS_LO (64 * ROWW)
#define WS_HI (2 * 64 * ROWW)
#define WS_LO (WS_HI + 128 * ROWW)
#define SMEM_WORDS (WS_LO + 128 * ROWW)        // 26112 words = 104448 B

// ---------------- scratch -----------------------------------------------------
__device__ float g_hw[(size_t)NODES * C];
__device__ float g_agg[(size_t)NODES * C];
__device__ float g_dinv[NODES];
__device__ int   g_ideg[NODES];
__device__ int   g_scan[NODES];
__device__ int   g_bsum[256];
__device__ int   g_off[NODES + 1];
__device__ int   g_cur[NODES];
__device__ int   g_esrc[EDGES];
__device__ float g_enorm[EDGES];
__device__ __align__(16) float g_stats[2 * C];
__device__ __align__(16) float g_ss[2 * C];
__device__ int   g_is64;

// ---------------- helpers ------------------------------------------------------
__device__ __forceinline__ void split2(float a, float b, uint32_t& hi, uint32_t& lo) {
    __nv_bfloat16 ah = __float2bfloat16(a);
    __nv_bfloat16 bh = __float2bfloat16(b);
    __nv_bfloat16 al = __float2bfloat16(a - __bfloat162float(ah));
    __nv_bfloat16 bl = __float2bfloat16(b - __bfloat162float(bh));
    hi = (uint32_t)__bfloat16_as_ushort(ah) | ((uint32_t)__bfloat16_as_ushort(bh) << 16);
    lo = (uint32_t)__bfloat16_as_ushort(al) | ((uint32_t)__bfloat16_as_ushort(bl) << 16);
}

__device__ __forceinline__ void mma_bf16(float* d, const uint32_t* a, const uint32_t* b) {
    asm volatile(
        "mma.sync.aligned.m16n8k16.row.col.f32.bf16.bf16.f32 "
        "{%0,%1,%2,%3}, {%4,%5,%6,%7}, {%8,%9}, {%0,%1,%2,%3};"
        : "+f"(d[0]), "+f"(d[1]), "+f"(d[2]), "+f"(d[3])
        : "r"(a[0]), "r"(a[1]), "r"(a[2]), "r"(a[3]), "r"(b[0]), "r"(b[1]));
}

// ---------------- dtype detection + zero deg ------------------------------------
__global__ void k_detect(const int* __restrict__ ei32) {
    if (blockIdx.x == 0) {
        __shared__ int acc;
        if (threadIdx.x == 0) acc = 0;
        __syncthreads();
        if (threadIdx.x < 256) {
            int v = ei32[2 * threadIdx.x + 1];
            if (v != 0) atomicOr(&acc, 1);
        }
        __syncthreads();
        if (threadIdx.x == 0) g_is64 = (acc == 0) ? 1 : 0;
    }
    int i = blockIdx.x * blockDim.x + threadIdx.x;
    if (i < NODES) g_ideg[i] = 0;
}

__device__ __forceinline__ int load_idx(const void* ei, long long pos) {
    if (g_is64) return (int)((const long long*)ei)[pos];
    return ((const int*)ei)[pos];
}

// ---------------- degree / CSR ----------------------------------------------------
__global__ void k_deg(const void* __restrict__ ei) {
    int e = blockIdx.x * blockDim.x + threadIdx.x;
    if (e < EDGES) {
        int d = load_idx(ei, (long long)EDGES + e);
        if ((unsigned)d < NODES) atomicAdd(&g_ideg[d], 1);
    }
}

__global__ void k_scan1() {
    __shared__ int s[SCAN_BLK];
    int tid = threadIdx.x;
    int i = blockIdx.x * SCAN_BLK + tid;
    s[tid] = (i < NODES) ? g_ideg[i] : 0;
    __syncthreads();
#pragma unroll
    for (int d = 1; d < SCAN_BLK; d <<= 1) {
        int t = (tid >= d) ? s[tid - d] : 0;
        __syncthreads();
        s[tid] += t;
        __syncthreads();
    }
    if (i < NODES) g_scan[i] = s[tid];
    if (tid == SCAN_BLK - 1) g_bsum[blockIdx.x] = s[tid];
}

__global__ void k_scan2() {
    __shared__ int s[256];
    int tid = threadIdx.x;
    s[tid] = (tid < NBLK1) ? g_bsum[tid] : 0;
    __syncthreads();
#pragma unroll
    for (int d = 1; d < 256; d <<= 1) {
        int t = (tid >= d) ? s[tid - d] : 0;
        __syncthreads();
        s[tid] += t;
        __syncthreads();
    }
    if (tid < NBLK1) g_bsum[tid] = s[tid];
}

// also computes dinv and zeroes g_stats (before first k_aggr)
__global__ void k_scan3() {
    int i = blockIdx.x * blockDim.x + threadIdx.x;
    if (i < NODES) {
        int blk = i / SCAN_BLK;
        int add = (blk > 0) ? g_bsum[blk - 1] : 0;
        g_off[i + 1] = g_scan[i] + add;
        g_cur[i] = 0;
        if (i == 0) g_off[0] = 0;
        g_dinv[i] = rsqrtf((float)g_ideg[i] + 1.0f);
    }
    if (i < 2 * C) g_stats[i] = 0.0f;
}

__global__ void k_fill(const void* __restrict__ ei) {
    int e = blockIdx.x * blockDim.x + threadIdx.x;
    if (e >= EDGES) return;
    int src = load_idx(ei, e);
    int dst = load_idx(ei, (long long)EDGES + e);
    if ((unsigned)src >= NODES || (unsigned)dst >= NODES) return;
    int pos = g_off[dst] + atomicAdd(&g_cur[dst], 1);
    g_esrc[pos] = src;
    g_enorm[pos] = g_dinv[src] * g_dinv[dst];
}

// ---------------- mma.sync GEMM: g_hw = norm(h) @ W --------------------------------
// MTILE=64, 102KB smem -> 2 CTAs/SM for cross-CTA stage/MMA overlap.
__global__ void __launch_bounds__(256, 2) k_gemm_mma(const float* __restrict__ x,
                                                     int use_x,
                                                     const float* __restrict__ W) {
    extern __shared__ __align__(16) uint32_t sw[];
    const int tid = threadIdx.x;
    const int wid = tid >> 5;
    const int lane = tid & 31;
    const int g = lane >> 2;
    const int tc = lane & 3;
    const int wm = wid & 1;       // row half (32 rows)
    const int wn = wid >> 1;      // col quarter (32 cols)

    // ---- stage W^T hi/lo once: thread owns outcol n = tid&127, k-half tid>>7 ----
    {
        const int n = tid & 127;
        const int kh = tid >> 7;
#pragma unroll 8
        for (int k2 = 0; k2 < 32; k2++) {
            const int k = kh * 64 + k2 * 2;
            float w0 = __ldg(W + (size_t)k * C + n);
            float w1 = __ldg(W + (size_t)(k + 1) * C + n);
            uint32_t hp, lp;
            split2(w0, w1, hp, lp);
            sw[WS_HI + n * ROWW + kh * 32 + k2] = hp;
            sw[WS_LO + n * ROWW + kh * 32 + k2] = lp;
        }
    }

    const float* __restrict__ hsrc = use_x ? x : (const float*)g_agg;

    for (int tile = blockIdx.x; tile < NTILES; tile += gridDim.x) {
        const int base = tile * MTILE;
        const int rem = min(MTILE, NODES - base);

        __syncthreads();  // prior tile's frag loads done before restage

        // ---- stage A tile: 64 rows x 32 float4, coalesced; fused BN+ReLU ----
#pragma unroll
        for (int it = 0; it < 8; it++) {
            const int f = it * 256 + tid;
            const int row = f >> 5;
            const int q4 = f & 31;
            float4 v;
            if (row < rem) {
                v = __ldg((const float4*)(hsrc + (size_t)(base + row) * C) + q4);
                if (!use_x) {
                    const float4 sc = ((const float4*)g_ss)[q4];
                    const float4 sh = ((const float4*)g_ss)[32 + q4];
                    v.x = fmaxf(fmaf(v.x, sc.x, sh.x), 0.f);
                    v.y = fmaxf(fmaf(v.y, sc.y, sh.y), 0.f);
                    v.z = fmaxf(fmaf(v.z, sc.z, sh.z), 0.f);
                    v.w = fmaxf(fmaf(v.w, sc.w, sh.w), 0.f);
                }
            } else {
                v = make_float4(0.f, 0.f, 0.f, 0.f);
            }
            uint32_t h0, l0, h1, l1;
            split2(v.x, v.y, h0, l0);
            split2(v.z, v.w, h1, l1);
            const int p = row * ROWW + q4 * 2;
            sw[AS_HI + p] = h0;  sw[AS_HI + p + 1] = h1;
            sw[AS_LO + p] = l0;  sw[AS_LO + p + 1] = l1;
        }
        __syncthreads();

        // ---- mainloop: 8 k16-steps, warp tile 32x32 = 2m x 4n frags ----
        float acc[2][4][4];
#pragma unroll
        for (int mf = 0; mf < 2; mf++)
#pragma unroll
            for (int nf = 0; nf < 4; nf++)
#pragma unroll
                for (int j = 0; j < 4; j++) acc[mf][nf][j] = 0.f;

#pragma unroll
        for (int ks = 0; ks < 8; ks++) {
            uint32_t ah[2][4], al[2][4], bh[4][2], bl[4][2];
            const int cb = ks * 8 + tc;
#pragma unroll
            for (int mf = 0; mf < 2; mf++) {
                const int r = wm * 32 + mf * 16 + g;
                ah[mf][0] = sw[AS_HI + r * ROWW + cb];
                ah[mf][1] = sw[AS_HI + (r + 8) * ROWW + cb];
                ah[mf][2] = sw[AS_HI + r * ROWW + cb + 4];
                ah[mf][3] = sw[AS_HI + (r + 8) * ROWW + cb + 4];
                al[mf][0] = sw[AS_LO + r * ROWW + cb];
                al[mf][1] = sw[AS_LO + (r + 8) * ROWW + cb];
                al[mf][2] = sw[AS_LO + r * ROWW + cb + 4];
                al[mf][3] = sw[AS_LO + (r + 8) * ROWW + cb + 4];
            }
#pragma unroll
            for (int nf = 0; nf < 4; nf++) {
                const int n = wn * 32 + nf * 8 + g;
                bh[nf][0] = sw[WS_HI + n * ROWW + cb];
                bh[nf][1] = sw[WS_HI + n * ROWW + cb + 4];
                bl[nf][0] = sw[WS_LO + n * ROWW + cb];
                bl[nf][1] = sw[WS_LO + n * ROWW + cb + 4];
            }
#pragma unroll
            for (int mf = 0; mf < 2; mf++)
#pragma unroll
                for (int nf = 0; nf < 4; nf++) {
                    mma_bf16(acc[mf][nf], ah[mf], bh[nf]);
                    mma_bf16(acc[mf][nf], ah[mf], bl[nf]);
                    mma_bf16(acc[mf][nf], al[mf], bh[nf]);
                }
        }

        // ---- epilogue: D[m][n] -> g_hw[node][outcol] ----
#pragma unroll
        for (int mf = 0; mf < 2; mf++) {
            const int m0 = wm * 32 + mf * 16 + g;
#pragma unroll
            for (int nf = 0; nf < 4; nf++) {
                const int cc = wn * 32 + nf * 8 + tc * 2;
                if (m0 < rem) {
                    float2 v = make_float2(acc[mf][nf][0], acc[mf][nf][1]);
                    *(float2*)(g_hw + (size_t)(base + m0) * C + cc) = v;
                }
                if (m0 + 8 < rem) {
                    float2 v = make_float2(acc[mf][nf][2], acc[mf][nf][3]);
                    *(float2*)(g_hw + (size_t)(base + m0 + 8) * C + cc) = v;
                }
            }
        }
    }
}

// ---------------- gather aggregate + self-loop + bias + fused BN stats ----------
__global__ void __launch_bounds__(256) k_aggr(const float* __restrict__ b) {
    __shared__ float sm[2 * C];
    if (threadIdx.x < 2 * C) sm[threadIdx.x] = 0.f;
    __syncthreads();

    const int warp = threadIdx.x >> 5;
    const int lane = threadIdx.x & 31;
    const float4 bb = __ldg((const float4*)b + lane);

    float4 ts = make_float4(0.f, 0.f, 0.f, 0.f);
    float4 ts2 = make_float4(0.f, 0.f, 0.f, 0.f);

    for (int d = blockIdx.x * 8 + warp; d < NODES; d += gridDim.x * 8) {
        const int beg = g_off[d], end = g_off[d + 1];
        float s = g_dinv[d];
        s *= s;
        float4 acc = __ldg((const float4*)(g_hw + (size_t)d * C) + lane);
        acc.x = fmaf(acc.x, s, bb.x);
        acc.y = fmaf(acc.y, s, bb.y);
        acc.z = fmaf(acc.z, s, bb.z);
        acc.w = fmaf(acc.w, s, bb.w);

        int e = beg;
        for (; e + 4 <= end; e += 4) {
            const int s0 = g_esrc[e], s1 = g_esrc[e + 1], s2 = g_esrc[e + 2], s3 = g_esrc[e + 3];
            const float n0 = g_enorm[e], n1 = g_enorm[e + 1], n2 = g_enorm[e + 2], n3 = g_enorm[e + 3];
            const float4 v0 = __ldg((const float4*)(g_hw + (size_t)s0 * C) + lane);
            const float4 v1 = __ldg((const float4*)(g_hw + (size_t)s1 * C) + lane);
            const float4 v2 = __ldg((const float4*)(g_hw + (size_t)s2 * C) + lane);
            const float4 v3 = __ldg((const float4*)(g_hw + (size_t)s3 * C) + lane);
            acc.x = fmaf(v0.x, n0, acc.x); acc.y = fmaf(v0.y, n0, acc.y);
            acc.z = fmaf(v0.z, n0, acc.z); acc.w = fmaf(v0.w, n0, acc.w);
            acc.x = fmaf(v1.x, n1, acc.x); acc.y = fmaf(v1.y, n1, acc.y);
            acc.z = fmaf(v1.z, n1, acc.z); acc.w = fmaf(v1.w, n1, acc.w);
            acc.x = fmaf(v2.x, n2, acc.x); acc.y = fmaf(v2.y, n2, acc.y);
            acc.z = fmaf(v2.z, n2, acc.z); acc.w = fmaf(v2.w, n2, acc.w);
            acc.x = fmaf(v3.x, n3, acc.x); acc.y = fmaf(v3.y, n3, acc.y);
            acc.z = fmaf(v3.z, n3, acc.z); acc.w = fmaf(v3.w, n3, acc.w);
        }
        for (; e < end; e++) {
            const int s0 = g_esrc[e];
            const float n0 = g_enorm[e];
            const float4 v0 = __ldg((const float4*)(g_hw + (size_t)s0 * C) + lane);
            acc.x = fmaf(v0.x, n0, acc.x); acc.y = fmaf(v0.y, n0, acc.y);
            acc.z = fmaf(v0.z, n0, acc.z); acc.w = fmaf(v0.w, n0, acc.w);
        }

        *((float4*)(g_agg + (size_t)d * C) + lane) = acc;

        ts.x += acc.x; ts.y += acc.y; ts.z += acc.z; ts.w += acc.w;
        ts2.x = fmaf(acc.x, acc.x, ts2.x); ts2.y = fmaf(acc.y, acc.y, ts2.y);
        ts2.z = fmaf(acc.z, acc.z, ts2.z); ts2.w = fmaf(acc.w, acc.w, ts2.w);
    }

    const int c0 = lane * 4;
    atomicAdd(&sm[c0 + 0], ts.x);  atomicAdd(&sm[c0 + 1], ts.y);
    atomicAdd(&sm[c0 + 2], ts.z);  atomicAdd(&sm[c0 + 3], ts.w);
    atomicAdd(&sm[C + c0 + 0], ts2.x);  atomicAdd(&sm[C + c0 + 1], ts2.y);
    atomicAdd(&sm[C + c0 + 2], ts2.z);  atomicAdd(&sm[C + c0 + 3], ts2.w);
    __syncthreads();
    if (threadIdx.x < 2 * C) atomicAdd(&g_stats[threadIdx.x], sm[threadIdx.x]);
}

// ---------------- BN finalize (also re-zeros stats for next layer) ---------------
__global__ void k_bnfin(const float* __restrict__ gamma, const float* __restrict__ beta) {
    int c = threadIdx.x;
    if (c < C) {
        const float inv_n = 1.0f / (float)NODES;
        float mean = g_stats[c] * inv_n;
        float var = g_stats[C + c] * inv_n - mean * mean;
        float sc = gamma[c] * rsqrtf(var + BN_EPS);
        g_ss[c] = sc;
        g_ss[C + c] = fmaf(-mean, sc, beta[c]);
        g_stats[c] = 0.f;
        g_stats[C + c] = 0.f;
    }
}

// ---------------- final normalize + ReLU -> d_out --------------------------------
__global__ void k_norm(float* __restrict__ dout) {
    int i = blockIdx.x * blockDim.x + threadIdx.x;
    if (i >= NODES * 32) return;
    int q = i & 31;
    float4 v = *((const float4*)g_agg + i);
    float4 sc = *((const float4*)g_ss + q);
    float4 sh = *((const float4*)(g_ss + C) + q);
    v.x = fmaxf(fmaf(v.x, sc.x, sh.x), 0.f);
    v.y = fmaxf(fmaf(v.y, sc.y, sh.y), 0.f);
    v.z = fmaxf(fmaf(v.z, sc.z, sh.z), 0.f);
    v.w = fmaxf(fmaf(v.w, sc.w, sh.w), 0.f);
    *((float4*)dout + i) = v;
}

// ---------------- launch -----------------------------------------------------------
extern "C" void kernel_launch(void* const* d_in, const int* in_sizes, int n_in,
                              void* d_out, int out_size) {
    const float* x = (const float*)d_in[0];
    const void* ei = d_in[1];
    const float* W[3]  = {(const float*)d_in[2],  (const float*)d_in[6],  (const float*)d_in[10]};
    const float* b[3]  = {(const float*)d_in[3],  (const float*)d_in[7],  (const float*)d_in[11]};
    const float* gm[3] = {(const float*)d_in[4],  (const float*)d_in[8],  (const float*)d_in[12]};
    const float* bt[3] = {(const float*)d_in[5],  (const float*)d_in[9],  (const float*)d_in[13]};

    cudaFuncSetAttribute(k_gemm_mma, cudaFuncAttributeMaxDynamicSharedMemorySize,
                         SMEM_WORDS * 4);

    const int vblk = (NODES * 32 + 255) / 256;

    k_detect<<<(NODES + 255) / 256, 256>>>((const int*)ei);
    k_deg<<<(EDGES + 255) / 256, 256>>>(ei);
    k_scan1<<<NBLK1, SCAN_BLK>>>();
    k_scan2<<<1, 256>>>();
    k_scan3<<<(NODES + 255) / 256, 256>>>();
    k_fill<<<(EDGES + 255) / 256, 256>>>(ei);

    for (int L = 0; L < 3; L++) {
        k_gemm_mma<<<296, 256, SMEM_WORDS * 4>>>(x, L == 0 ? 1 : 0, W[L]);
        k_aggr<<<592, 256>>>(b[L]);
        k_bnfin<<<1, 128>>>(gm[L], bt[L]);
    }
    k_norm<<<vblk, 256>>>((float*)d_out);
}

// round 9
// speedup vs baseline: 4.5262x; 1.0114x over previous
#include <cuda_runtime.h>
#include <cuda_bf16.h>
#include <cstdint>

#define NODES 100000
#define EDGES 1600000
#define C 128
#define BN_EPS 1e-5f
#define SCAN_BLK 512
#define NBLK1 ((NODES + SCAN_BLK - 1) / SCAN_BLK)

#define MTILE 64
#define NTILES ((NODES + MTILE - 1) / MTILE)   // 1563

// smem word (uint32) layout: padded row stride 68 -> conflict-free frag loads
#define ROWW 68
#define AS_HI 0
#define AS_LO (64 * ROWW)
#define WS_HI (2 * 64 * ROWW)
#define WS_LO (WS_HI + 128 * ROWW)
#define SMEM_WORDS (WS_LO + 128 * ROWW)        // 26112 words = 104448 B

// ---------------- scratch -----------------------------------------------------
__device__ float g_hw[(size_t)NODES * C];
__device__ float g_agg[(size_t)NODES * C];
__device__ float g_dinv[NODES];
__device__ int   g_ideg[NODES];
__device__ int   g_scan[NODES];
__device__ int   g_bsum[256];
__device__ int   g_off[NODES + 1];
__device__ int   g_cur[NODES];
__device__ int   g_esrc[EDGES];
__device__ float g_enorm[EDGES];
__device__ __align__(16) float g_stats[2 * C];
__device__ __align__(16) float g_ss[2 * C];
__device__ int   g_is64;

// ---------------- helpers ------------------------------------------------------
// packed split: hi word = {bf16(b)<<16 | bf16(a)}, lo = residual pair
__device__ __forceinline__ void split2(float a, float b, uint32_t& hi, uint32_t& lo) {
    uint32_t h;
    asm("cvt.rn.bf16x2.f32 %0, %1, %2;" : "=r"(h) : "f"(b), "f"(a));
    float af = __uint_as_float(h << 16);
    float bf = __uint_as_float(h & 0xffff0000u);
    asm("cvt.rn.bf16x2.f32 %0, %1, %2;" : "=r"(lo) : "f"(b - bf), "f"(a - af));
    hi = h;
}

__device__ __forceinline__ void mma_bf16(float* d, const uint32_t* a, const uint32_t* b) {
    asm volatile(
        "mma.sync.aligned.m16n8k16.row.col.f32.bf16.bf16.f32 "
        "{%0,%1,%2,%3}, {%4,%5,%6,%7}, {%8,%9}, {%0,%1,%2,%3};"
        : "+f"(d[0]), "+f"(d[1]), "+f"(d[2]), "+f"(d[3])
        : "r"(a[0]), "r"(a[1]), "r"(a[2]), "r"(a[3]), "r"(b[0]), "r"(b[1]));
}

// ---------------- dtype detection + zero deg ------------------------------------
__global__ void k_detect(const int* __restrict__ ei32) {
    if (blockIdx.x == 0) {
        __shared__ int acc;
        if (threadIdx.x == 0) acc = 0;
        __syncthreads();
        if (threadIdx.x < 256) {
            int v = ei32[2 * threadIdx.x + 1];
            if (v != 0) atomicOr(&acc, 1);
        }
        __syncthreads();
        if (threadIdx.x == 0) g_is64 = (acc == 0) ? 1 : 0;
    }
    int i = blockIdx.x * blockDim.x + threadIdx.x;
    if (i < NODES) g_ideg[i] = 0;
}

__device__ __forceinline__ int load_idx(const void* ei, long long pos) {
    if (g_is64) return (int)((const long long*)ei)[pos];
    return ((const int*)ei)[pos];
}

// ---------------- degree / CSR ----------------------------------------------------
__global__ void k_deg(const void* __restrict__ ei) {
    int e = blockIdx.x * blockDim.x + threadIdx.x;
    if (e < EDGES) {
        int d = load_idx(ei, (long long)EDGES + e);
        if ((unsigned)d < NODES) atomicAdd(&g_ideg[d], 1);
    }
}

__global__ void k_scan1() {
    __shared__ int s[SCAN_BLK];
    int tid = threadIdx.x;
    int i = blockIdx.x * SCAN_BLK + tid;
    s[tid] = (i < NODES) ? g_ideg[i] : 0;
    __syncthreads();
#pragma unroll
    for (int d = 1; d < SCAN_BLK; d <<= 1) {
        int t = (tid >= d) ? s[tid - d] : 0;
        __syncthreads();
        s[tid] += t;
        __syncthreads();
    }
    if (i < NODES) g_scan[i] = s[tid];
    if (tid == SCAN_BLK - 1) g_bsum[blockIdx.x] = s[tid];
}

__global__ void k_scan2() {
    __shared__ int s[256];
    int tid = threadIdx.x;
    s[tid] = (tid < NBLK1) ? g_bsum[tid] : 0;
    __syncthreads();
#pragma unroll
    for (int d = 1; d < 256; d <<= 1) {
        int t = (tid >= d) ? s[tid - d] : 0;
        __syncthreads();
        s[tid] += t;
        __syncthreads();
    }
    if (tid < NBLK1) g_bsum[tid] = s[tid];
}

// also computes dinv and zeroes g_stats (before first k_aggr)
__global__ void k_scan3() {
    int i = blockIdx.x * blockDim.x + threadIdx.x;
    if (i < NODES) {
        int blk = i / SCAN_BLK;
        int add = (blk > 0) ? g_bsum[blk - 1] : 0;
        g_off[i + 1] = g_scan[i] + add;
        g_cur[i] = 0;
        if (i == 0) g_off[0] = 0;
        g_dinv[i] = rsqrtf((float)g_ideg[i] + 1.0f);
    }
    if (i < 2 * C) g_stats[i] = 0.0f;
}

__global__ void k_fill(const void* __restrict__ ei) {
    int e = blockIdx.x * blockDim.x + threadIdx.x;
    if (e >= EDGES) return;
    int src = load_idx(ei, e);
    int dst = load_idx(ei, (long long)EDGES + e);
    if ((unsigned)src >= NODES || (unsigned)dst >= NODES) return;
    int pos = g_off[dst] + atomicAdd(&g_cur[dst], 1);
    g_esrc[pos] = src;
    g_enorm[pos] = g_dinv[src] * g_dinv[dst];
}

// ---------------- mma.sync GEMM: g_hw = norm(h) @ W --------------------------------
__global__ void __launch_bounds__(256, 2) k_gemm_mma(const float* __restrict__ x,
                                                     int use_x,
                                                     const float* __restrict__ W) {
    extern __shared__ __align__(16) uint32_t sw[];
    const int tid = threadIdx.x;
    const int wid = tid >> 5;
    const int lane = tid & 31;
    const int g = lane >> 2;
    const int tc = lane & 3;
    const int wm = wid & 1;       // row half (32 rows)
    const int wn = wid >> 1;      // col quarter (32 cols)

    // ---- stage W^T hi/lo once ----
    {
        const int n = tid & 127;
        const int kh = tid >> 7;
#pragma unroll 8
        for (int k2 = 0; k2 < 32; k2++) {
            const int k = kh * 64 + k2 * 2;
            float w0 = __ldg(W + (size_t)k * C + n);
            float w1 = __ldg(W + (size_t)(k + 1) * C + n);
            uint32_t hp, lp;
            split2(w0, w1, hp, lp);
            sw[WS_HI + n * ROWW + kh * 32 + k2] = hp;
            sw[WS_LO + n * ROWW + kh * 32 + k2] = lp;
        }
    }

    const float* __restrict__ hsrc = use_x ? x : (const float*)g_agg;

    for (int tile = blockIdx.x; tile < NTILES; tile += gridDim.x) {
        const int base = tile * MTILE;
        const int rem = min(MTILE, NODES - base);

        __syncthreads();

        // ---- stage A tile: 64 rows x 32 float4, coalesced; fused BN+ReLU ----
#pragma unroll
        for (int it = 0; it < 8; it++) {
            const int f = it * 256 + tid;
            const int row = f >> 5;
            const int q4 = f & 31;
            float4 v;
            if (row < rem) {
                v = __ldg((const float4*)(hsrc + (size_t)(base + row) * C) + q4);
                if (!use_x) {
                    const float4 sc = ((const float4*)g_ss)[q4];
                    const float4 sh = ((const float4*)g_ss)[32 + q4];
                    v.x = fmaxf(fmaf(v.x, sc.x, sh.x), 0.f);
                    v.y = fmaxf(fmaf(v.y, sc.y, sh.y), 0.f);
                    v.z = fmaxf(fmaf(v.z, sc.z, sh.z), 0.f);
                    v.w = fmaxf(fmaf(v.w, sc.w, sh.w), 0.f);
                }
            } else {
                v = make_float4(0.f, 0.f, 0.f, 0.f);
            }
            uint32_t h0, l0, h1, l1;
            split2(v.x, v.y, h0, l0);
            split2(v.z, v.w, h1, l1);
            const int p = row * ROWW + q4 * 2;
            sw[AS_HI + p] = h0;  sw[AS_HI + p + 1] = h1;
            sw[AS_LO + p] = l0;  sw[AS_LO + p + 1] = l1;
        }
        __syncthreads();

        // ---- mainloop: 8 k16-steps, warp tile 32x32 ----
        float acc[2][4][4];
#pragma unroll
        for (int mf = 0; mf < 2; mf++)
#pragma unroll
            for (int nf = 0; nf < 4; nf++)
#pragma unroll
                for (int j = 0; j < 4; j++) acc[mf][nf][j] = 0.f;

#pragma unroll
        for (int ks = 0; ks < 8; ks++) {
            uint32_t ah[2][4], al[2][4], bh[4][2], bl[4][2];
            const int cb = ks * 8 + tc;
#pragma unroll
            for (int mf = 0; mf < 2; mf++) {
                const int r = wm * 32 + mf * 16 + g;
                ah[mf][0] = sw[AS_HI + r * ROWW + cb];
                ah[mf][1] = sw[AS_HI + (r + 8) * ROWW + cb];
                ah[mf][2] = sw[AS_HI + r * ROWW + cb + 4];
                ah[mf][3] = sw[AS_HI + (r + 8) * ROWW + cb + 4];
                al[mf][0] = sw[AS_LO + r * ROWW + cb];
                al[mf][1] = sw[AS_LO + (r + 8) * ROWW + cb];
                al[mf][2] = sw[AS_LO + r * ROWW + cb + 4];
                al[mf][3] = sw[AS_LO + (r + 8) * ROWW + cb + 4];
            }
#pragma unroll
            for (int nf = 0; nf < 4; nf++) {
                const int n = wn * 32 + nf * 8 + g;
                bh[nf][0] = sw[WS_HI + n * ROWW + cb];
                bh[nf][1] = sw[WS_HI + n * ROWW + cb + 4];
                bl[nf][0] = sw[WS_LO + n * ROWW + cb];
                bl[nf][1] = sw[WS_LO + n * ROWW + cb + 4];
            }
#pragma unroll
            for (int mf = 0; mf < 2; mf++)
#pragma unroll
                for (int nf = 0; nf < 4; nf++) {
                    mma_bf16(acc[mf][nf], ah[mf], bh[nf]);
                    mma_bf16(acc[mf][nf], ah[mf], bl[nf]);
                    mma_bf16(acc[mf][nf], al[mf], bh[nf]);
                }
        }

        // ---- epilogue ----
#pragma unroll
        for (int mf = 0; mf < 2; mf++) {
            const int m0 = wm * 32 + mf * 16 + g;
#pragma unroll
            for (int nf = 0; nf < 4; nf++) {
                const int cc = wn * 32 + nf * 8 + tc * 2;
                if (m0 < rem) {
                    float2 v = make_float2(acc[mf][nf][0], acc[mf][nf][1]);
                    *(float2*)(g_hw + (size_t)(base + m0) * C + cc) = v;
                }
                if (m0 + 8 < rem) {
                    float2 v = make_float2(acc[mf][nf][2], acc[mf][nf][3]);
                    *(float2*)(g_hw + (size_t)(base + m0 + 8) * C + cc) = v;
                }
            }
        }
    }
}

// ---------------- gather aggregate + self-loop + bias + fused BN stats ----------
__global__ void __launch_bounds__(256) k_aggr(const float* __restrict__ b) {
    __shared__ float sm[2 * C];
    if (threadIdx.x < 2 * C) sm[threadIdx.x] = 0.f;
    __syncthreads();

    const int warp = threadIdx.x >> 5;
    const int lane = threadIdx.x & 31;
    const float4 bb = __ldg((const float4*)b + lane);

    float4 ts = make_float4(0.f, 0.f, 0.f, 0.f);
    float4 ts2 = make_float4(0.f, 0.f, 0.f, 0.f);

    for (int d = blockIdx.x * 8 + warp; d < NODES; d += gridDim.x * 8) {
        const int beg = g_off[d], end = g_off[d + 1];
        float s = g_dinv[d];
        s *= s;
        float4 acc = __ldg((const float4*)(g_hw + (size_t)d * C) + lane);
        acc.x = fmaf(acc.x, s, bb.x);
        acc.y = fmaf(acc.y, s, bb.y);
        acc.z = fmaf(acc.z, s, bb.z);
        acc.w = fmaf(acc.w, s, bb.w);

        int e = beg;
        for (; e + 4 <= end; e += 4) {
            const int s0 = g_esrc[e], s1 = g_esrc[e + 1], s2 = g_esrc[e + 2], s3 = g_esrc[e + 3];
            const float n0 = g_enorm[e], n1 = g_enorm[e + 1], n2 = g_enorm[e + 2], n3 = g_enorm[e + 3];
            const float4 v0 = __ldg((const float4*)(g_hw + (size_t)s0 * C) + lane);
            const float4 v1 = __ldg((const float4*)(g_hw + (size_t)s1 * C) + lane);
            const float4 v2 = __ldg((const float4*)(g_hw + (size_t)s2 * C) + lane);
            const float4 v3 = __ldg((const float4*)(g_hw + (size_t)s3 * C) + lane);
            acc.x = fmaf(v0.x, n0, acc.x); acc.y = fmaf(v0.y, n0, acc.y);
            acc.z = fmaf(v0.z, n0, acc.z); acc.w = fmaf(v0.w, n0, acc.w);
            acc.x = fmaf(v1.x, n1, acc.x); acc.y = fmaf(v1.y, n1, acc.y);
            acc.z = fmaf(v1.z, n1, acc.z); acc.w = fmaf(v1.w, n1, acc.w);
            acc.x = fmaf(v2.x, n2, acc.x); acc.y = fmaf(v2.y, n2, acc.y);
            acc.z = fmaf(v2.z, n2, acc.z); acc.w = fmaf(v2.w, n2, acc.w);
            acc.x = fmaf(v3.x, n3, acc.x); acc.y = fmaf(v3.y, n3, acc.y);
            acc.z = fmaf(v3.z, n3, acc.z); acc.w = fmaf(v3.w, n3, acc.w);
        }
        for (; e < end; e++) {
            const int s0 = g_esrc[e];
            const float n0 = g_enorm[e];
            const float4 v0 = __ldg((const float4*)(g_hw + (size_t)s0 * C) + lane);
            acc.x = fmaf(v0.x, n0, acc.x); acc.y = fmaf(v0.y, n0, acc.y);
            acc.z = fmaf(v0.z, n0, acc.z); acc.w = fmaf(v0.w, n0, acc.w);
        }

        *((float4*)(g_agg + (size_t)d * C) + lane) = acc;

        ts.x += acc.x; ts.y += acc.y; ts.z += acc.z; ts.w += acc.w;
        ts2.x = fmaf(acc.x, acc.x, ts2.x); ts2.y = fmaf(acc.y, acc.y, ts2.y);
        ts2.z = fmaf(acc.z, acc.z, ts2.z); ts2.w = fmaf(acc.w, acc.w, ts2.w);
    }

    const int c0 = lane * 4;
    atomicAdd(&sm[c0 + 0], ts.x);  atomicAdd(&sm[c0 + 1], ts.y);
    atomicAdd(&sm[c0 + 2], ts.z);  atomicAdd(&sm[c0 + 3], ts.w);
    atomicAdd(&sm[C + c0 + 0], ts2.x);  atomicAdd(&sm[C + c0 + 1], ts2.y);
    atomicAdd(&sm[C + c0 + 2], ts2.z);  atomicAdd(&sm[C + c0 + 3], ts2.w);
    __syncthreads();
    if (threadIdx.x < 2 * C) atomicAdd(&g_stats[threadIdx.x], sm[threadIdx.x]);
}

// ---------------- BN finalize (re-zeros stats for next layer) --------------------
__global__ void k_bnfin(const float* __restrict__ gamma, const float* __restrict__ beta) {
    int c = threadIdx.x;
    if (c < C) {
        const float inv_n = 1.0f / (float)NODES;
        float mean = g_stats[c] * inv_n;
        float var = g_stats[C + c] * inv_n - mean * mean;
        float sc = gamma[c] * rsqrtf(var + BN_EPS);
        g_ss[c] = sc;
        g_ss[C + c] = fmaf(-mean, sc, beta[c]);
        g_stats[c] = 0.f;
        g_stats[C + c] = 0.f;
    }
}

// ---------------- final normalize + ReLU -> d_out --------------------------------
__global__ void k_norm(float* __restrict__ dout) {
    int i = blockIdx.x * blockDim.x + threadIdx.x;
    if (i >= NODES * 32) return;
    int q = i & 31;
    float4 v = *((const float4*)g_agg + i);
    float4 sc = *((const float4*)g_ss + q);
    float4 sh = *((const float4*)(g_ss + C) + q);
    v.x = fmaxf(fmaf(v.x, sc.x, sh.x), 0.f);
    v.y = fmaxf(fmaf(v.y, sc.y, sh.y), 0.f);
    v.z = fmaxf(fmaf(v.z, sc.z, sh.z), 0.f);
    v.w = fmaxf(fmaf(v.w, sc.w, sh.w), 0.f);
    *((float4*)dout + i) = v;
}

// ---------------- launch -----------------------------------------------------------
extern "C" void kernel_launch(void* const* d_in, const int* in_sizes, int n_in,
                              void* d_out, int out_size) {
    const float* x = (const float*)d_in[0];
    const void* ei = d_in[1];
    const float* W[3]  = {(const float*)d_in[2],  (const float*)d_in[6],  (const float*)d_in[10]};
    const float* b[3]  = {(const float*)d_in[3],  (const float*)d_in[7],  (const float*)d_in[11]};
    const float* gm[3] = {(const float*)d_in[4],  (const float*)d_in[8],  (const float*)d_in[12]};
    const float* bt[3] = {(const float*)d_in[5],  (const float*)d_in[9],  (const float*)d_in[13]};

    static cudaStream_t s2 = 0;
    static cudaEvent_t evFork = 0, evJoin = 0;
    if (!s2) {
        cudaStreamCreateWithFlags(&s2, cudaStreamNonBlocking);
        cudaEventCreateWithFlags(&evFork, cudaEventDisableTiming);
        cudaEventCreateWithFlags(&evJoin, cudaEventDisableTiming);
        cudaFuncSetAttribute(k_gemm_mma, cudaFuncAttributeMaxDynamicSharedMemorySize,
                             SMEM_WORDS * 4);
    }

    const int vblk = (NODES * 32 + 255) / 256;

    // fork: CSR build on s2, concurrent with layer-0 GEMM on main stream
    cudaEventRecord(evFork, 0);
    cudaStreamWaitEvent(s2, evFork, 0);
    k_detect<<<(NODES + 255) / 256, 256, 0, s2>>>((const int*)ei);
    k_deg<<<(EDGES + 255) / 256, 256, 0, s2>>>(ei);
    k_scan1<<<NBLK1, SCAN_BLK, 0, s2>>>();
    k_scan2<<<1, 256, 0, s2>>>();
    k_scan3<<<(NODES + 255) / 256, 256, 0, s2>>>();
    k_fill<<<(EDGES + 255) / 256, 256, 0, s2>>>(ei);
    cudaEventRecord(evJoin, s2);

    k_gemm_mma<<<296, 256, SMEM_WORDS * 4>>>(x, 1, W[0]);
    cudaStreamWaitEvent(0, evJoin, 0);  // join before first aggregation

    for (int L = 0; L < 3; L++) {
        if (L > 0) k_gemm_mma<<<296, 256, SMEM_WORDS * 4>>>(x, 0, W[L]);
        k_aggr<<<592, 256>>>(b[L]);
        k_bnfin<<<1, 128>>>(gm[L], bt[L]);
    }
    k_norm<<<vblk, 256>>>((float*)d_out);
}

// round 10
// speedup vs baseline: 5.5604x; 1.2285x over previous
#include <cuda_runtime.h>
#include <cuda_bf16.h>
#include <cuda_fp16.h>
#include <cstdint>

#define NODES 100000
#define EDGES 1600000
#define C 128
#define BN_EPS 1e-5f
#define SCAN_BLK 512
#define NBLK1 ((NODES + SCAN_BLK - 1) / SCAN_BLK)

#define MTILE 64
#define NTILES ((NODES + MTILE - 1) / MTILE)   // 1563

#define AGGR_BLOCKS 592

// smem word (uint32) layout: padded row stride 68 -> conflict-free frag loads
#define ROWW 68
#define AS_HI 0
#define AS_LO (64 * ROWW)
#define WS_HI (2 * 64 * ROWW)
#define WS_LO (WS_HI + 128 * ROWW)
#define SMEM_WORDS (WS_LO + 128 * ROWW)        // 26112 words = 104448 B

// ---------------- scratch -----------------------------------------------------
__device__ __half g_hw16[(size_t)NODES * C];
__device__ float g_agg[(size_t)NODES * C];
__device__ float g_dinv[NODES];
__device__ int   g_ideg[NODES];
__device__ int   g_scan[NODES];
__device__ int   g_bsum[256];
__device__ int   g_off[NODES + 1];
__device__ int   g_cur[NODES];
__device__ int   g_esrc[EDGES];
__device__ float g_enorm[EDGES];
__device__ __align__(16) float g_stats[2 * C];
__device__ __align__(16) float g_ss[2 * C];
__device__ int   g_is64;
__device__ int   g_done;

// ---------------- helpers ------------------------------------------------------
__device__ __forceinline__ void split2(float a, float b, uint32_t& hi, uint32_t& lo) {
    uint32_t h;
    asm("cvt.rn.bf16x2.f32 %0, %1, %2;" : "=r"(h) : "f"(b), "f"(a));
    float af = __uint_as_float(h << 16);
    float bf = __uint_as_float(h & 0xffff0000u);
    asm("cvt.rn.bf16x2.f32 %0, %1, %2;" : "=r"(lo) : "f"(b - bf), "f"(a - af));
    hi = h;
}

__device__ __forceinline__ void mma_bf16(float* d, const uint32_t* a, const uint32_t* b) {
    asm volatile(
        "mma.sync.aligned.m16n8k16.row.col.f32.bf16.bf16.f32 "
        "{%0,%1,%2,%3}, {%4,%5,%6,%7}, {%8,%9}, {%0,%1,%2,%3};"
        : "+f"(d[0]), "+f"(d[1]), "+f"(d[2]), "+f"(d[3])
        : "r"(a[0]), "r"(a[1]), "r"(a[2]), "r"(a[3]), "r"(b[0]), "r"(b[1]));
}

// gather 8 bytes (4 halves) -> float4
__device__ __forceinline__ float4 ld_row16(const __half* base, int lane) {
    const uint2 u = __ldg((const uint2*)base + lane);
    const float2 p0 = __half22float2(*(const half2*)&u.x);
    const float2 p1 = __half22float2(*(const half2*)&u.y);
    return make_float4(p0.x, p0.y, p1.x, p1.y);
}

// ---------------- dtype detection + zero deg ------------------------------------
__global__ void k_detect(const int* __restrict__ ei32) {
    if (blockIdx.x == 0) {
        __shared__ int acc;
        if (threadIdx.x == 0) acc = 0;
        __syncthreads();
        if (threadIdx.x < 256) {
            int v = ei32[2 * threadIdx.x + 1];
            if (v != 0) atomicOr(&acc, 1);
        }
        __syncthreads();
        if (threadIdx.x == 0) { g_is64 = (acc == 0) ? 1 : 0; g_done = 0; }
    }
    int i = blockIdx.x * blockDim.x + threadIdx.x;
    if (i < NODES) g_ideg[i] = 0;
}

__device__ __forceinline__ int load_idx(const void* ei, long long pos) {
    if (g_is64) return (int)((const long long*)ei)[pos];
    return ((const int*)ei)[pos];
}

// ---------------- degree / CSR ----------------------------------------------------
__global__ void k_deg(const void* __restrict__ ei) {
    int e = blockIdx.x * blockDim.x + threadIdx.x;
    if (e < EDGES) {
        int d = load_idx(ei, (long long)EDGES + e);
        if ((unsigned)d < NODES) atomicAdd(&g_ideg[d], 1);
    }
}

__global__ void k_scan1() {
    __shared__ int s[SCAN_BLK];
    int tid = threadIdx.x;
    int i = blockIdx.x * SCAN_BLK + tid;
    s[tid] = (i < NODES) ? g_ideg[i] : 0;
    __syncthreads();
#pragma unroll
    for (int d = 1; d < SCAN_BLK; d <<= 1) {
        int t = (tid >= d) ? s[tid - d] : 0;
        __syncthreads();
        s[tid] += t;
        __syncthreads();
    }
    if (i < NODES) g_scan[i] = s[tid];
    if (tid == SCAN_BLK - 1) g_bsum[blockIdx.x] = s[tid];
}

__global__ void k_scan2() {
    __shared__ int s[256];
    int tid = threadIdx.x;
    s[tid] = (tid < NBLK1) ? g_bsum[tid] : 0;
    __syncthreads();
#pragma unroll
    for (int d = 1; d < 256; d <<= 1) {
        int t = (tid >= d) ? s[tid - d] : 0;
        __syncthreads();
        s[tid] += t;
        __syncthreads();
    }
    if (tid < NBLK1) g_bsum[tid] = s[tid];
}

__global__ void k_scan3() {
    int i = blockIdx.x * blockDim.x + threadIdx.x;
    if (i < NODES) {
        int blk = i / SCAN_BLK;
        int add = (blk > 0) ? g_bsum[blk - 1] : 0;
        g_off[i + 1] = g_scan[i] + add;
        g_cur[i] = 0;
        if (i == 0) g_off[0] = 0;
        g_dinv[i] = rsqrtf((float)g_ideg[i] + 1.0f);
    }
    if (i < 2 * C) g_stats[i] = 0.0f;
}

__global__ void k_fill(const void* __restrict__ ei) {
    int e = blockIdx.x * blockDim.x + threadIdx.x;
    if (e >= EDGES) return;
    int src = load_idx(ei, e);
    int dst = load_idx(ei, (long long)EDGES + e);
    if ((unsigned)src >= NODES || (unsigned)dst >= NODES) return;
    int pos = g_off[dst] + atomicAdd(&g_cur[dst], 1);
    g_esrc[pos] = src;
    g_enorm[pos] = g_dinv[src] * g_dinv[dst];
}

// ---------------- mma.sync GEMM: g_hw16 = norm(h) @ W -----------------------------
__global__ void __launch_bounds__(256, 2) k_gemm_mma(const float* __restrict__ x,
                                                     int use_x,
                                                     const float* __restrict__ W) {
    extern __shared__ __align__(16) uint32_t sw[];
    const int tid = threadIdx.x;
    const int wid = tid >> 5;
    const int lane = tid & 31;
    const int g = lane >> 2;
    const int tc = lane & 3;
    const int wm = wid & 1;
    const int wn = wid >> 1;

    // ---- stage W^T hi/lo once ----
    {
        const int n = tid & 127;
        const int kh = tid >> 7;
#pragma unroll 8
        for (int k2 = 0; k2 < 32; k2++) {
            const int k = kh * 64 + k2 * 2;
            float w0 = __ldg(W + (size_t)k * C + n);
            float w1 = __ldg(W + (size_t)(k + 1) * C + n);
            uint32_t hp, lp;
            split2(w0, w1, hp, lp);
            sw[WS_HI + n * ROWW + kh * 32 + k2] = hp;
            sw[WS_LO + n * ROWW + kh * 32 + k2] = lp;
        }
    }

    const float* __restrict__ hsrc = use_x ? x : (const float*)g_agg;

    for (int tile = blockIdx.x; tile < NTILES; tile += gridDim.x) {
        const int base = tile * MTILE;
        const int rem = min(MTILE, NODES - base);

        __syncthreads();

        // ---- stage A tile; fused BN+ReLU for layers > 0 ----
#pragma unroll
        for (int it = 0; it < 8; it++) {
            const int f = it * 256 + tid;
            const int row = f >> 5;
            const int q4 = f & 31;
            float4 v;
            if (row < rem) {
                v = __ldg((const float4*)(hsrc + (size_t)(base + row) * C) + q4);
                if (!use_x) {
                    const float4 sc = ((const float4*)g_ss)[q4];
                    const float4 sh = ((const float4*)g_ss)[32 + q4];
                    v.x = fmaxf(fmaf(v.x, sc.x, sh.x), 0.f);
                    v.y = fmaxf(fmaf(v.y, sc.y, sh.y), 0.f);
                    v.z = fmaxf(fmaf(v.z, sc.z, sh.z), 0.f);
                    v.w = fmaxf(fmaf(v.w, sc.w, sh.w), 0.f);
                }
            } else {
                v = make_float4(0.f, 0.f, 0.f, 0.f);
            }
            uint32_t h0, l0, h1, l1;
            split2(v.x, v.y, h0, l0);
            split2(v.z, v.w, h1, l1);
            const int p = row * ROWW + q4 * 2;
            sw[AS_HI + p] = h0;  sw[AS_HI + p + 1] = h1;
            sw[AS_LO + p] = l0;  sw[AS_LO + p + 1] = l1;
        }
        __syncthreads();

        // ---- mainloop ----
        float acc[2][4][4];
#pragma unroll
        for (int mf = 0; mf < 2; mf++)
#pragma unroll
            for (int nf = 0; nf < 4; nf++)
#pragma unroll
                for (int j = 0; j < 4; j++) acc[mf][nf][j] = 0.f;

#pragma unroll
        for (int ks = 0; ks < 8; ks++) {
            uint32_t ah[2][4], al[2][4], bh[4][2], bl[4][2];
            const int cb = ks * 8 + tc;
#pragma unroll
            for (int mf = 0; mf < 2; mf++) {
                const int r = wm * 32 + mf * 16 + g;
                ah[mf][0] = sw[AS_HI + r * ROWW + cb];
                ah[mf][1] = sw[AS_HI + (r + 8) * ROWW + cb];
                ah[mf][2] = sw[AS_HI + r * ROWW + cb + 4];
                ah[mf][3] = sw[AS_HI + (r + 8) * ROWW + cb + 4];
                al[mf][0] = sw[AS_LO + r * ROWW + cb];
                al[mf][1] = sw[AS_LO + (r + 8) * ROWW + cb];
                al[mf][2] = sw[AS_LO + r * ROWW + cb + 4];
                al[mf][3] = sw[AS_LO + (r + 8) * ROWW + cb + 4];
            }
#pragma unroll
            for (int nf = 0; nf < 4; nf++) {
                const int n = wn * 32 + nf * 8 + g;
                bh[nf][0] = sw[WS_HI + n * ROWW + cb];
                bh[nf][1] = sw[WS_HI + n * ROWW + cb + 4];
                bl[nf][0] = sw[WS_LO + n * ROWW + cb];
                bl[nf][1] = sw[WS_LO + n * ROWW + cb + 4];
            }
#pragma unroll
            for (int mf = 0; mf < 2; mf++)
#pragma unroll
                for (int nf = 0; nf < 4; nf++) {
                    mma_bf16(acc[mf][nf], ah[mf], bh[nf]);
                    mma_bf16(acc[mf][nf], ah[mf], bl[nf]);
                    mma_bf16(acc[mf][nf], al[mf], bh[nf]);
                }
        }

        // ---- epilogue: fp16 output ----
#pragma unroll
        for (int mf = 0; mf < 2; mf++) {
            const int m0 = wm * 32 + mf * 16 + g;
#pragma unroll
            for (int nf = 0; nf < 4; nf++) {
                const int cc = wn * 32 + nf * 8 + tc * 2;
                if (m0 < rem) {
                    half2 p = __floats2half2_rn(acc[mf][nf][0], acc[mf][nf][1]);
                    *(half2*)(g_hw16 + (size_t)(base + m0) * C + cc) = p;
                }
                if (m0 + 8 < rem) {
                    half2 p = __floats2half2_rn(acc[mf][nf][2], acc[mf][nf][3]);
                    *(half2*)(g_hw16 + (size_t)(base + m0 + 8) * C + cc) = p;
                }
            }
        }
    }
}

// ------ gather aggregate + self-loop + bias + BN stats + last-block BN finalize ---
__global__ void __launch_bounds__(256) k_aggr(const float* __restrict__ b,
                                              const float* __restrict__ gamma,
                                              const float* __restrict__ beta) {
    __shared__ float sm[2 * C];
    __shared__ bool isLast;
    if (threadIdx.x < 2 * C) sm[threadIdx.x] = 0.f;
    __syncthreads();

    const int warp = threadIdx.x >> 5;
    const int lane = threadIdx.x & 31;
    const float4 bb = __ldg((const float4*)b + lane);

    float4 ts = make_float4(0.f, 0.f, 0.f, 0.f);
    float4 ts2 = make_float4(0.f, 0.f, 0.f, 0.f);

    for (int d = blockIdx.x * 8 + warp; d < NODES; d += gridDim.x * 8) {
        const int beg = g_off[d], end = g_off[d + 1];
        float s = g_dinv[d];
        s *= s;
        float4 acc = ld_row16(g_hw16 + (size_t)d * C, lane);
        acc.x = fmaf(acc.x, s, bb.x);
        acc.y = fmaf(acc.y, s, bb.y);
        acc.z = fmaf(acc.z, s, bb.z);
        acc.w = fmaf(acc.w, s, bb.w);

        int e = beg;
        for (; e + 4 <= end; e += 4) {
            const int s0 = g_esrc[e], s1 = g_esrc[e + 1], s2 = g_esrc[e + 2], s3 = g_esrc[e + 3];
            const float n0 = g_enorm[e], n1 = g_enorm[e + 1], n2 = g_enorm[e + 2], n3 = g_enorm[e + 3];
            const float4 v0 = ld_row16(g_hw16 + (size_t)s0 * C, lane);
            const float4 v1 = ld_row16(g_hw16 + (size_t)s1 * C, lane);
            const float4 v2 = ld_row16(g_hw16 + (size_t)s2 * C, lane);
            const float4 v3 = ld_row16(g_hw16 + (size_t)s3 * C, lane);
            acc.x = fmaf(v0.x, n0, acc.x); acc.y = fmaf(v0.y, n0, acc.y);
            acc.z = fmaf(v0.z, n0, acc.z); acc.w = fmaf(v0.w, n0, acc.w);
            acc.x = fmaf(v1.x, n1, acc.x); acc.y = fmaf(v1.y, n1, acc.y);
            acc.z = fmaf(v1.z, n1, acc.z); acc.w = fmaf(v1.w, n1, acc.w);
            acc.x = fmaf(v2.x, n2, acc.x); acc.y = fmaf(v2.y, n2, acc.y);
            acc.z = fmaf(v2.z, n2, acc.z); acc.w = fmaf(v2.w, n2, acc.w);
            acc.x = fmaf(v3.x, n3, acc.x); acc.y = fmaf(v3.y, n3, acc.y);
            acc.z = fmaf(v3.z, n3, acc.z); acc.w = fmaf(v3.w, n3, acc.w);
        }
        for (; e < end; e++) {
            const int s0 = g_esrc[e];
            const float n0 = g_enorm[e];
            const float4 v0 = ld_row16(g_hw16 + (size_t)s0 * C, lane);
            acc.x = fmaf(v0.x, n0, acc.x); acc.y = fmaf(v0.y, n0, acc.y);
            acc.z = fmaf(v0.z, n0, acc.z); acc.w = fmaf(v0.w, n0, acc.w);
        }

        *((float4*)(g_agg + (size_t)d * C) + lane) = acc;

        ts.x += acc.x; ts.y += acc.y; ts.z += acc.z; ts.w += acc.w;
        ts2.x = fmaf(acc.x, acc.x, ts2.x); ts2.y = fmaf(acc.y, acc.y, ts2.y);
        ts2.z = fmaf(acc.z, acc.z, ts2.z); ts2.w = fmaf(acc.w, acc.w, ts2.w);
    }

    const int c0 = lane * 4;
    atomicAdd(&sm[c0 + 0], ts.x);  atomicAdd(&sm[c0 + 1], ts.y);
    atomicAdd(&sm[c0 + 2], ts.z);  atomicAdd(&sm[c0 + 3], ts.w);
    atomicAdd(&sm[C + c0 + 0], ts2.x);  atomicAdd(&sm[C + c0 + 1], ts2.y);
    atomicAdd(&sm[C + c0 + 2], ts2.z);  atomicAdd(&sm[C + c0 + 3], ts2.w);
    __syncthreads();
    if (threadIdx.x < 2 * C) atomicAdd(&g_stats[threadIdx.x], sm[threadIdx.x]);

    // ---- last-block-done: finalize BN affine here ----
    if (threadIdx.x == 0) {
        __threadfence();
        int t = atomicAdd(&g_done, 1);
        isLast = (t == gridDim.x - 1);
    }
    __syncthreads();
    if (isLast) {
        int c = threadIdx.x;
        if (c < C) {
            const float inv_n = 1.0f / (float)NODES;
            float mean = __ldcg(&g_stats[c]) * inv_n;
            float var = __ldcg(&g_stats[C + c]) * inv_n - mean * mean;
            float sc = __ldg(gamma + c) * rsqrtf(var + BN_EPS);
            g_ss[c] = sc;
            g_ss[C + c] = fmaf(-mean, sc, __ldg(beta + c));
            g_stats[c] = 0.f;
            g_stats[C + c] = 0.f;
        }
        if (threadIdx.x == 255) g_done = 0;
    }
}

// ---------------- final normalize + ReLU -> d_out --------------------------------
__global__ void k_norm(float* __restrict__ dout) {
    int i = blockIdx.x * blockDim.x + threadIdx.x;
    if (i >= NODES * 32) return;
    int q = i & 31;
    float4 v = *((const float4*)g_agg + i);
    float4 sc = *((const float4*)g_ss + q);
    float4 sh = *((const float4*)(g_ss + C) + q);
    v.x = fmaxf(fmaf(v.x, sc.x, sh.x), 0.f);
    v.y = fmaxf(fmaf(v.y, sc.y, sh.y), 0.f);
    v.z = fmaxf(fmaf(v.z, sc.z, sh.z), 0.f);
    v.w = fmaxf(fmaf(v.w, sc.w, sh.w), 0.f);
    *((float4*)dout + i) = v;
}

// ---------------- launch -----------------------------------------------------------
extern "C" void kernel_launch(void* const* d_in, const int* in_sizes, int n_in,
                              void* d_out, int out_size) {
    const float* x = (const float*)d_in[0];
    const void* ei = d_in[1];
    const float* W[3]  = {(const float*)d_in[2],  (const float*)d_in[6],  (const float*)d_in[10]};
    const float* b[3]  = {(const float*)d_in[3],  (const float*)d_in[7],  (const float*)d_in[11]};
    const float* gm[3] = {(const float*)d_in[4],  (const float*)d_in[8],  (const float*)d_in[12]};
    const float* bt[3] = {(const float*)d_in[5],  (const float*)d_in[9],  (const float*)d_in[13]};

    static cudaStream_t s2 = 0;
    static cudaEvent_t evFork = 0, evJoin = 0;
    if (!s2) {
        cudaStreamCreateWithFlags(&s2, cudaStreamNonBlocking);
        cudaEventCreateWithFlags(&evFork, cudaEventDisableTiming);
        cudaEventCreateWithFlags(&evJoin, cudaEventDisableTiming);
        cudaFuncSetAttribute(k_gemm_mma, cudaFuncAttributeMaxDynamicSharedMemorySize,
                             SMEM_WORDS * 4);
    }

    const int vblk = (NODES * 32 + 255) / 256;

    // fork: CSR build on s2, concurrent with layer-0 GEMM
    cudaEventRecord(evFork, 0);
    cudaStreamWaitEvent(s2, evFork, 0);
    k_detect<<<(NODES + 255) / 256, 256, 0, s2>>>((const int*)ei);
    k_deg<<<(EDGES + 255) / 256, 256, 0, s2>>>(ei);
    k_scan1<<<NBLK1, SCAN_BLK, 0, s2>>>();
    k_scan2<<<1, 256, 0, s2>>>();
    k_scan3<<<(NODES + 255) / 256, 256, 0, s2>>>();
    k_fill<<<(EDGES + 255) / 256, 256, 0, s2>>>(ei);
    cudaEventRecord(evJoin, s2);

    k_gemm_mma<<<296, 256, SMEM_WORDS * 4>>>(x, 1, W[0]);
    cudaStreamWaitEvent(0, evJoin, 0);

    for (int L = 0; L < 3; L++) {
        if (L > 0) k_gemm_mma<<<296, 256, SMEM_WORDS * 4>>>(x, 0, W[L]);
        k_aggr<<<AGGR_BLOCKS, 256>>>(b[L], gm[L], bt[L]);
    }
    k_norm<<<vblk, 256>>>((float*)d_out);
}

// round 11
// speedup vs baseline: 6.3204x; 1.1367x over previous
#include <cuda_runtime.h>
#include <cuda_bf16.h>
#include <cuda_fp16.h>
#include <cstdint>

#define NODES 100000
#define EDGES 1600000
#define C 128
#define BN_EPS 1e-5f
#define SCAN_BLK 512
#define NBLK1 ((NODES + SCAN_BLK - 1) / SCAN_BLK)

#define MTILE 64
#define NTILES ((NODES + MTILE - 1) / MTILE)   // 1563
#define GEMM_BLOCKS 296

#define AGGR_BLOCKS 592

// smem word (uint32) layout: padded row stride 68 -> conflict-free frag loads
#define ROWW 68
#define AS_HI 0
#define AS_LO (64 * ROWW)
#define WS_HI (2 * 64 * ROWW)
#define WS_LO (WS_HI + 128 * ROWW)
#define SMEM_WORDS (WS_LO + 128 * ROWW)        // 26112 words = 104448 B

// ---------------- scratch -----------------------------------------------------
__device__ __half g_hw16[(size_t)NODES * C];
__device__ float g_agg[(size_t)NODES * C];
__device__ float g_dinv[NODES];
__device__ int   g_ideg[NODES];
__device__ int   g_scan[NODES];
__device__ int   g_bsum[256];
__device__ int   g_off[NODES + 1];
__device__ int   g_cur[NODES];
__device__ int   g_esrc[EDGES];
__device__ float g_enorm[EDGES];
__device__ __align__(16) float g_stats[2 * C];
__device__ __align__(16) float g_ss[2 * C];
__device__ int   g_is64;
__device__ int   g_done;

// ---------------- helpers ------------------------------------------------------
__device__ __forceinline__ void split2(float a, float b, uint32_t& hi, uint32_t& lo) {
    uint32_t h;
    asm("cvt.rn.bf16x2.f32 %0, %1, %2;" : "=r"(h) : "f"(b), "f"(a));
    float af = __uint_as_float(h << 16);
    float bf = __uint_as_float(h & 0xffff0000u);
    asm("cvt.rn.bf16x2.f32 %0, %1, %2;" : "=r"(lo) : "f"(b - bf), "f"(a - af));
    hi = h;
}

__device__ __forceinline__ void mma_bf16(float* d, const uint32_t* a, const uint32_t* b) {
    asm volatile(
        "mma.sync.aligned.m16n8k16.row.col.f32.bf16.bf16.f32 "
        "{%0,%1,%2,%3}, {%4,%5,%6,%7}, {%8,%9}, {%0,%1,%2,%3};"
        : "+f"(d[0]), "+f"(d[1]), "+f"(d[2]), "+f"(d[3])
        : "r"(a[0]), "r"(a[1]), "r"(a[2]), "r"(a[3]), "r"(b[0]), "r"(b[1]));
}

// gather 8 bytes (4 halves) -> float4
__device__ __forceinline__ float4 ld_row16(const __half* base, int lane) {
    const uint2 u = __ldg((const uint2*)base + lane);
    const float2 p0 = __half22float2(*(const half2*)&u.x);
    const float2 p1 = __half22float2(*(const half2*)&u.y);
    return make_float4(p0.x, p0.y, p1.x, p1.y);
}

// ---------------- dtype detection + zero deg ------------------------------------
__global__ void k_detect(const int* __restrict__ ei32) {
    if (blockIdx.x == 0) {
        __shared__ int acc;
        if (threadIdx.x == 0) acc = 0;
        __syncthreads();
        if (threadIdx.x < 256) {
            int v = ei32[2 * threadIdx.x + 1];
            if (v != 0) atomicOr(&acc, 1);
        }
        __syncthreads();
        if (threadIdx.x == 0) { g_is64 = (acc == 0) ? 1 : 0; g_done = 0; }
    }
    int i = blockIdx.x * blockDim.x + threadIdx.x;
    if (i < NODES) g_ideg[i] = 0;
}

__device__ __forceinline__ int load_idx(const void* ei, long long pos) {
    if (g_is64) return (int)((const long long*)ei)[pos];
    return ((const int*)ei)[pos];
}

// ---------------- degree / CSR ----------------------------------------------------
__global__ void k_deg(const void* __restrict__ ei) {
    int e = blockIdx.x * blockDim.x + threadIdx.x;
    if (e < EDGES) {
        int d = load_idx(ei, (long long)EDGES + e);
        if ((unsigned)d < NODES) atomicAdd(&g_ideg[d], 1);
    }
}

__global__ void k_scan1() {
    __shared__ int s[SCAN_BLK];
    int tid = threadIdx.x;
    int i = blockIdx.x * SCAN_BLK + tid;
    s[tid] = (i < NODES) ? g_ideg[i] : 0;
    __syncthreads();
#pragma unroll
    for (int d = 1; d < SCAN_BLK; d <<= 1) {
        int t = (tid >= d) ? s[tid - d] : 0;
        __syncthreads();
        s[tid] += t;
        __syncthreads();
    }
    if (i < NODES) g_scan[i] = s[tid];
    if (tid == SCAN_BLK - 1) g_bsum[blockIdx.x] = s[tid];
}

__global__ void k_scan2() {
    __shared__ int s[256];
    int tid = threadIdx.x;
    s[tid] = (tid < NBLK1) ? g_bsum[tid] : 0;
    __syncthreads();
#pragma unroll
    for (int d = 1; d < 256; d <<= 1) {
        int t = (tid >= d) ? s[tid - d] : 0;
        __syncthreads();
        s[tid] += t;
        __syncthreads();
    }
    if (tid < NBLK1) g_bsum[tid] = s[tid];
}

__global__ void k_scan3() {
    int i = blockIdx.x * blockDim.x + threadIdx.x;
    if (i < NODES) {
        int blk = i / SCAN_BLK;
        int add = (blk > 0) ? g_bsum[blk - 1] : 0;
        g_off[i + 1] = g_scan[i] + add;
        g_cur[i] = 0;
        if (i == 0) g_off[0] = 0;
        g_dinv[i] = rsqrtf((float)g_ideg[i] + 1.0f);
    }
    if (i < 2 * C) g_stats[i] = 0.0f;
}

__global__ void k_fill(const void* __restrict__ ei) {
    int e = blockIdx.x * blockDim.x + threadIdx.x;
    if (e >= EDGES) return;
    int src = load_idx(ei, e);
    int dst = load_idx(ei, (long long)EDGES + e);
    if ((unsigned)src >= NODES || (unsigned)dst >= NODES) return;
    int pos = g_off[dst] + atomicAdd(&g_cur[dst], 1);
    g_esrc[pos] = src;
    g_enorm[pos] = g_dinv[src] * g_dinv[dst];
}

// ---------------- mma.sync GEMM with register-prefetch pipeline -------------------
__global__ void __launch_bounds__(256, 2) k_gemm_mma(const float* __restrict__ x,
                                                     int use_x,
                                                     const float* __restrict__ W) {
    extern __shared__ __align__(16) uint32_t sw[];
    const int tid = threadIdx.x;
    const int wid = tid >> 5;
    const int lane = tid & 31;
    const int g = lane >> 2;
    const int tc = lane & 3;
    const int wm = wid & 1;
    const int wn = wid >> 1;

    // ---- stage W^T hi/lo once ----
    {
        const int n = tid & 127;
        const int kh = tid >> 7;
#pragma unroll 8
        for (int k2 = 0; k2 < 32; k2++) {
            const int k = kh * 64 + k2 * 2;
            float w0 = __ldg(W + (size_t)k * C + n);
            float w1 = __ldg(W + (size_t)(k + 1) * C + n);
            uint32_t hp, lp;
            split2(w0, w1, hp, lp);
            sw[WS_HI + n * ROWW + kh * 32 + k2] = hp;
            sw[WS_LO + n * ROWW + kh * 32 + k2] = lp;
        }
    }

    const float* __restrict__ hsrc = use_x ? x : (const float*)g_agg;
    // per-thread staging coordinates: f = it*256+tid, row = f>>5, q4 = f&31
    const int prow[2] = {tid >> 5, (256 + tid) >> 5};  // rows for it even/odd pattern
    // thread handles f = it*256+tid for it=0..7: rows (it*256+tid)>>5 = it*8 + (tid>>5)
    const int row0 = tid >> 5;      // + it*8
    const int q4 = tid & 31;
    (void)prow;

    float4 sc4 = make_float4(1.f, 0.f, 0.f, 0.f), sh4;
    if (!use_x) {
        sc4 = ((const float4*)g_ss)[q4];
        sh4 = ((const float4*)g_ss)[32 + q4];
    } else {
        sc4 = make_float4(1.f, 1.f, 1.f, 1.f);
        sh4 = make_float4(0.f, 0.f, 0.f, 0.f);
    }

    // ---- prefetch first tile's A into registers ----
    float4 pf[8];
    int tile = blockIdx.x;
    {
        const int base = tile * MTILE;
        const int rem = (tile < NTILES) ? min(MTILE, NODES - base) : 0;
#pragma unroll
        for (int it = 0; it < 8; it++) {
            const int row = it * 8 + row0;
            pf[it] = (row < rem)
                ? __ldg((const float4*)(hsrc + (size_t)(base + row) * C) + q4)
                : make_float4(0.f, 0.f, 0.f, 0.f);
        }
    }

    for (; tile < NTILES; tile += gridDim.x) {
        const int base = tile * MTILE;
        const int rem = min(MTILE, NODES - base);

        __syncthreads();  // previous mainloop's LDS reads complete

        // ---- split + STS from prefetched registers (BN+ReLU fused) ----
#pragma unroll
        for (int it = 0; it < 8; it++) {
            float4 v = pf[it];
            if (!use_x) {
                v.x = fmaxf(fmaf(v.x, sc4.x, sh4.x), 0.f);
                v.y = fmaxf(fmaf(v.y, sc4.y, sh4.y), 0.f);
                v.z = fmaxf(fmaf(v.z, sc4.z, sh4.z), 0.f);
                v.w = fmaxf(fmaf(v.w, sc4.w, sh4.w), 0.f);
            }
            uint32_t h0, l0, h1, l1;
            split2(v.x, v.y, h0, l0);
            split2(v.z, v.w, h1, l1);
            const int p = (it * 8 + row0) * ROWW + q4 * 2;
            sw[AS_HI + p] = h0;  sw[AS_HI + p + 1] = h1;
            sw[AS_LO + p] = l0;  sw[AS_LO + p + 1] = l1;
        }
        __syncthreads();

        // ---- issue next tile's prefetch (overlaps with mainloop below) ----
        const int ntile = tile + gridDim.x;
        if (ntile < NTILES) {
            const int nbase = ntile * MTILE;
            const int nrem = min(MTILE, NODES - nbase);
#pragma unroll
            for (int it = 0; it < 8; it++) {
                const int row = it * 8 + row0;
                pf[it] = (row < nrem)
                    ? __ldg((const float4*)(hsrc + (size_t)(nbase + row) * C) + q4)
                    : make_float4(0.f, 0.f, 0.f, 0.f);
            }
        }

        // ---- mainloop: 8 k16-steps, warp tile 32x32 ----
        float acc[2][4][4];
#pragma unroll
        for (int mf = 0; mf < 2; mf++)
#pragma unroll
            for (int nf = 0; nf < 4; nf++)
#pragma unroll
                for (int j = 0; j < 4; j++) acc[mf][nf][j] = 0.f;

#pragma unroll
        for (int ks = 0; ks < 8; ks++) {
            uint32_t ah[2][4], al[2][4], bh[4][2], bl[4][2];
            const int cb = ks * 8 + tc;
#pragma unroll
            for (int mf = 0; mf < 2; mf++) {
                const int r = wm * 32 + mf * 16 + g;
                ah[mf][0] = sw[AS_HI + r * ROWW + cb];
                ah[mf][1] = sw[AS_HI + (r + 8) * ROWW + cb];
                ah[mf][2] = sw[AS_HI + r * ROWW + cb + 4];
                ah[mf][3] = sw[AS_HI + (r + 8) * ROWW + cb + 4];
                al[mf][0] = sw[AS_LO + r * ROWW + cb];
                al[mf][1] = sw[AS_LO + (r + 8) * ROWW + cb];
                al[mf][2] = sw[AS_LO + r * ROWW + cb + 4];
                al[mf][3] = sw[AS_LO + (r + 8) * ROWW + cb + 4];
            }
#pragma unroll
            for (int nf = 0; nf < 4; nf++) {
                const int n = wn * 32 + nf * 8 + g;
                bh[nf][0] = sw[WS_HI + n * ROWW + cb];
                bh[nf][1] = sw[WS_HI + n * ROWW + cb + 4];
                bl[nf][0] = sw[WS_LO + n * ROWW + cb];
                bl[nf][1] = sw[WS_LO + n * ROWW + cb + 4];
            }
#pragma unroll
            for (int mf = 0; mf < 2; mf++)
#pragma unroll
                for (int nf = 0; nf < 4; nf++) {
                    mma_bf16(acc[mf][nf], ah[mf], bh[nf]);
                    mma_bf16(acc[mf][nf], ah[mf], bl[nf]);
                    mma_bf16(acc[mf][nf], al[mf], bh[nf]);
                }
        }

        // ---- epilogue: fp16 output ----
#pragma unroll
        for (int mf = 0; mf < 2; mf++) {
            const int m0 = wm * 32 + mf * 16 + g;
#pragma unroll
            for (int nf = 0; nf < 4; nf++) {
                const int cc = wn * 32 + nf * 8 + tc * 2;
                if (m0 < rem) {
                    half2 p = __floats2half2_rn(acc[mf][nf][0], acc[mf][nf][1]);
                    *(half2*)(g_hw16 + (size_t)(base + m0) * C + cc) = p;
                }
                if (m0 + 8 < rem) {
                    half2 p = __floats2half2_rn(acc[mf][nf][2], acc[mf][nf][3]);
                    *(half2*)(g_hw16 + (size_t)(base + m0 + 8) * C + cc) = p;
                }
            }
        }
    }
}

// ------ gather aggregate + self-loop + bias + BN stats + last-block BN finalize ---
__global__ void __launch_bounds__(256) k_aggr(const float* __restrict__ b,
                                              const float* __restrict__ gamma,
                                              const float* __restrict__ beta) {
    __shared__ float sm[2 * C];
    __shared__ bool isLast;
    if (threadIdx.x < 2 * C) sm[threadIdx.x] = 0.f;
    __syncthreads();

    const int warp = threadIdx.x >> 5;
    const int lane = threadIdx.x & 31;
    const float4 bb = __ldg((const float4*)b + lane);

    float4 ts = make_float4(0.f, 0.f, 0.f, 0.f);
    float4 ts2 = make_float4(0.f, 0.f, 0.f, 0.f);

    for (int d = blockIdx.x * 8 + warp; d < NODES; d += gridDim.x * 8) {
        const int beg = g_off[d], end = g_off[d + 1];
        float s = g_dinv[d];
        s *= s;
        float4 acc = ld_row16(g_hw16 + (size_t)d * C, lane);
        acc.x = fmaf(acc.x, s, bb.x);
        acc.y = fmaf(acc.y, s, bb.y);
        acc.z = fmaf(acc.z, s, bb.z);
        acc.w = fmaf(acc.w, s, bb.w);

        int e = beg;
        for (; e + 4 <= end; e += 4) {
            const int s0 = g_esrc[e], s1 = g_esrc[e + 1], s2 = g_esrc[e + 2], s3 = g_esrc[e + 3];
            const float n0 = g_enorm[e], n1 = g_enorm[e + 1], n2 = g_enorm[e + 2], n3 = g_enorm[e + 3];
            const float4 v0 = ld_row16(g_hw16 + (size_t)s0 * C, lane);
            const float4 v1 = ld_row16(g_hw16 + (size_t)s1 * C, lane);
            const float4 v2 = ld_row16(g_hw16 + (size_t)s2 * C, lane);
            const float4 v3 = ld_row16(g_hw16 + (size_t)s3 * C, lane);
            acc.x = fmaf(v0.x, n0, acc.x); acc.y = fmaf(v0.y, n0, acc.y);
            acc.z = fmaf(v0.z, n0, acc.z); acc.w = fmaf(v0.w, n0, acc.w);
            acc.x = fmaf(v1.x, n1, acc.x); acc.y = fmaf(v1.y, n1, acc.y);
            acc.z = fmaf(v1.z, n1, acc.z); acc.w = fmaf(v1.w, n1, acc.w);
            acc.x = fmaf(v2.x, n2, acc.x); acc.y = fmaf(v2.y, n2, acc.y);
            acc.z = fmaf(v2.z, n2, acc.z); acc.w = fmaf(v2.w, n2, acc.w);
            acc.x = fmaf(v3.x, n3, acc.x); acc.y = fmaf(v3.y, n3, acc.y);
            acc.z = fmaf(v3.z, n3, acc.z); acc.w = fmaf(v3.w, n3, acc.w);
        }
        for (; e < end; e++) {
            const int s0 = g_esrc[e];
            const float n0 = g_enorm[e];
            const float4 v0 = ld_row16(g_hw16 + (size_t)s0 * C, lane);
            acc.x = fmaf(v0.x, n0, acc.x); acc.y = fmaf(v0.y, n0, acc.y);
            acc.z = fmaf(v0.z, n0, acc.z); acc.w = fmaf(v0.w, n0, acc.w);
        }

        *((float4*)(g_agg + (size_t)d * C) + lane) = acc;

        ts.x += acc.x; ts.y += acc.y; ts.z += acc.z; ts.w += acc.w;
        ts2.x = fmaf(acc.x, acc.x, ts2.x); ts2.y = fmaf(acc.y, acc.y, ts2.y);
        ts2.z = fmaf(acc.z, acc.z, ts2.z); ts2.w = fmaf(acc.w, acc.w, ts2.w);
    }

    const int c0 = lane * 4;
    atomicAdd(&sm[c0 + 0], ts.x);  atomicAdd(&sm[c0 + 1], ts.y);
    atomicAdd(&sm[c0 + 2], ts.z);  atomicAdd(&sm[c0 + 3], ts.w);
    atomicAdd(&sm[C + c0 + 0], ts2.x);  atomicAdd(&sm[C + c0 + 1], ts2.y);
    atomicAdd(&sm[C + c0 + 2], ts2.z);  atomicAdd(&sm[C + c0 + 3], ts2.w);
    __syncthreads();
    if (threadIdx.x < 2 * C) atomicAdd(&g_stats[threadIdx.x], sm[threadIdx.x]);

    if (threadIdx.x == 0) {
        __threadfence();
        int t = atomicAdd(&g_done, 1);
        isLast = (t == gridDim.x - 1);
    }
    __syncthreads();
    if (isLast) {
        int c = threadIdx.x;
        if (c < C) {
            const float inv_n = 1.0f / (float)NODES;
            float mean = __ldcg(&g_stats[c]) * inv_n;
            float var = __ldcg(&g_stats[C + c]) * inv_n - mean * mean;
            float sc = __ldg(gamma + c) * rsqrtf(var + BN_EPS);
            g_ss[c] = sc;
            g_ss[C + c] = fmaf(-mean, sc, __ldg(beta + c));
            g_stats[c] = 0.f;
            g_stats[C + c] = 0.f;
        }
        if (threadIdx.x == 255) g_done = 0;
    }
}

// ---------------- final normalize + ReLU -> d_out --------------------------------
__global__ void k_norm(float* __restrict__ dout) {
    int i = blockIdx.x * blockDim.x + threadIdx.x;
    if (i >= NODES * 32) return;
    int q = i & 31;
    float4 v = *((const float4*)g_agg + i);
    float4 sc = *((const float4*)g_ss + q);
    float4 sh = *((const float4*)(g_ss + C) + q);
    v.x = fmaxf(fmaf(v.x, sc.x, sh.x), 0.f);
    v.y = fmaxf(fmaf(v.y, sc.y, sh.y), 0.f);
    v.z = fmaxf(fmaf(v.z, sc.z, sh.z), 0.f);
    v.w = fmaxf(fmaf(v.w, sc.w, sh.w), 0.f);
    *((float4*)dout + i) = v;
}

// ---------------- launch -----------------------------------------------------------
extern "C" void kernel_launch(void* const* d_in, const int* in_sizes, int n_in,
                              void* d_out, int out_size) {
    const float* x = (const float*)d_in[0];
    const void* ei = d_in[1];
    const float* W[3]  = {(const float*)d_in[2],  (const float*)d_in[6],  (const float*)d_in[10]};
    const float* b[3]  = {(const float*)d_in[3],  (const float*)d_in[7],  (const float*)d_in[11]};
    const float* gm[3] = {(const float*)d_in[4],  (const float*)d_in[8],  (const float*)d_in[12]};
    const float* bt[3] = {(const float*)d_in[5],  (const float*)d_in[9],  (const float*)d_in[13]};

    static cudaStream_t s2 = 0;
    static cudaEvent_t evFork = 0, evJoin = 0;
    if (!s2) {
        cudaStreamCreateWithFlags(&s2, cudaStreamNonBlocking);
        cudaEventCreateWithFlags(&evFork, cudaEventDisableTiming);
        cudaEventCreateWithFlags(&evJoin, cudaEventDisableTiming);
        cudaFuncSetAttribute(k_gemm_mma, cudaFuncAttributeMaxDynamicSharedMemorySize,
                             SMEM_WORDS * 4);
    }

    const int vblk = (NODES * 32 + 255) / 256;

    // fork: CSR build on s2, concurrent with layer-0 GEMM
    cudaEventRecord(evFork, 0);
    cudaStreamWaitEvent(s2, evFork, 0);
    k_detect<<<(NODES + 255) / 256, 256, 0, s2>>>((const int*)ei);
    k_deg<<<(EDGES + 255) / 256, 256, 0, s2>>>(ei);
    k_scan1<<<NBLK1, SCAN_BLK, 0, s2>>>();
    k_scan2<<<1, 256, 0, s2>>>();
    k_scan3<<<(NODES + 255) / 256, 256, 0, s2>>>();
    k_fill<<<(EDGES + 255) / 256, 256, 0, s2>>>(ei);
    cudaEventRecord(evJoin, s2);

    k_gemm_mma<<<GEMM_BLOCKS, 256, SMEM_WORDS * 4>>>(x, 1, W[0]);
    cudaStreamWaitEvent(0, evJoin, 0);

    for (int L = 0; L < 3; L++) {
        if (L > 0) k_gemm_mma<<<GEMM_BLOCKS, 256, SMEM_WORDS * 4>>>(x, 0, W[L]);
        k_aggr<<<AGGR_BLOCKS, 256>>>(b[L], gm[L], bt[L]);
    }
    k_norm<<<vblk, 256>>>((float*)d_out);
}

// round 12
// speedup vs baseline: 6.3794x; 1.0093x over previous
#include <cuda_runtime.h>
#include <cuda_bf16.h>
#include <cuda_fp16.h>
#include <cstdint>

#define NODES 100000
#define EDGES 1600000
#define C 128
#define BN_EPS 1e-5f
#define SCAN_BLK 512
#define NBLK1 ((NODES + SCAN_BLK - 1) / SCAN_BLK)

#define MTILE 64
#define NTILES ((NODES + MTILE - 1) / MTILE)   // 1563
#define GEMM_BLOCKS 148

#define AGGR_BLOCKS 592

// smem word (uint32) layout: padded row stride 68 -> conflict-free frag loads
#define ROWW 68
#define AS_HI 0
#define AS_LO (64 * ROWW)
#define WS_HI (2 * 64 * ROWW)
#define WS_LO (WS_HI + 128 * ROWW)
#define SMEM_WORDS (WS_LO + 128 * ROWW)        // 26112 words = 104448 B

// ---------------- scratch -----------------------------------------------------
__device__ __half g_hw16[(size_t)NODES * C];
__device__ float g_agg[(size_t)NODES * C];
__device__ float g_dinv[NODES];
__device__ int   g_ideg[NODES];
__device__ int   g_scan[NODES];
__device__ int   g_bsum[256];
__device__ int   g_off[NODES + 1];
__device__ int   g_cur[NODES];
__device__ int   g_esrc[EDGES];
__device__ float g_enorm[EDGES];
__device__ __align__(16) float g_stats[2 * C];
__device__ __align__(16) float g_ss[2 * C];
__device__ int   g_is64;
__device__ int   g_done;

// ---------------- helpers ------------------------------------------------------
__device__ __forceinline__ void split2(float a, float b, uint32_t& hi, uint32_t& lo) {
    uint32_t h;
    asm("cvt.rn.bf16x2.f32 %0, %1, %2;" : "=r"(h) : "f"(b), "f"(a));
    float af = __uint_as_float(h << 16);
    float bf = __uint_as_float(h & 0xffff0000u);
    asm("cvt.rn.bf16x2.f32 %0, %1, %2;" : "=r"(lo) : "f"(b - bf), "f"(a - af));
    hi = h;
}

__device__ __forceinline__ void mma_bf16(float* d, const uint32_t* a, const uint32_t* b) {
    asm volatile(
        "mma.sync.aligned.m16n8k16.row.col.f32.bf16.bf16.f32 "
        "{%0,%1,%2,%3}, {%4,%5,%6,%7}, {%8,%9}, {%0,%1,%2,%3};"
        : "+f"(d[0]), "+f"(d[1]), "+f"(d[2]), "+f"(d[3])
        : "r"(a[0]), "r"(a[1]), "r"(a[2]), "r"(a[3]), "r"(b[0]), "r"(b[1]));
}

// gather 8 bytes (4 halves) -> float4
__device__ __forceinline__ float4 ld_row16(const __half* base, int lane) {
    const uint2 u = __ldg((const uint2*)base + lane);
    const float2 p0 = __half22float2(*(const half2*)&u.x);
    const float2 p1 = __half22float2(*(const half2*)&u.y);
    return make_float4(p0.x, p0.y, p1.x, p1.y);
}

// ---------------- dtype detection + zero deg ------------------------------------
__global__ void k_detect(const int* __restrict__ ei32) {
    if (blockIdx.x == 0) {
        __shared__ int acc;
        if (threadIdx.x == 0) acc = 0;
        __syncthreads();
        if (threadIdx.x < 256) {
            int v = ei32[2 * threadIdx.x + 1];
            if (v != 0) atomicOr(&acc, 1);
        }
        __syncthreads();
        if (threadIdx.x == 0) { g_is64 = (acc == 0) ? 1 : 0; g_done = 0; }
    }
    int i = blockIdx.x * blockDim.x + threadIdx.x;
    if (i < NODES) g_ideg[i] = 0;
}

__device__ __forceinline__ int load_idx(const void* ei, long long pos) {
    if (g_is64) return (int)((const long long*)ei)[pos];
    return ((const int*)ei)[pos];
}

// ---------------- degree / CSR ----------------------------------------------------
__global__ void k_deg(const void* __restrict__ ei) {
    int e = blockIdx.x * blockDim.x + threadIdx.x;
    if (e < EDGES) {
        int d = load_idx(ei, (long long)EDGES + e);
        if ((unsigned)d < NODES) atomicAdd(&g_ideg[d], 1);
    }
}

__global__ void k_scan1() {
    __shared__ int s[SCAN_BLK];
    int tid = threadIdx.x;
    int i = blockIdx.x * SCAN_BLK + tid;
    s[tid] = (i < NODES) ? g_ideg[i] : 0;
    __syncthreads();
#pragma unroll
    for (int d = 1; d < SCAN_BLK; d <<= 1) {
        int t = (tid >= d) ? s[tid - d] : 0;
        __syncthreads();
        s[tid] += t;
        __syncthreads();
    }
    if (i < NODES) g_scan[i] = s[tid];
    if (tid == SCAN_BLK - 1) g_bsum[blockIdx.x] = s[tid];
}

__global__ void k_scan2() {
    __shared__ int s[256];
    int tid = threadIdx.x;
    s[tid] = (tid < NBLK1) ? g_bsum[tid] : 0;
    __syncthreads();
#pragma unroll
    for (int d = 1; d < 256; d <<= 1) {
        int t = (tid >= d) ? s[tid - d] : 0;
        __syncthreads();
        s[tid] += t;
        __syncthreads();
    }
    if (tid < NBLK1) g_bsum[tid] = s[tid];
}

__global__ void k_scan3() {
    int i = blockIdx.x * blockDim.x + threadIdx.x;
    if (i < NODES) {
        int blk = i / SCAN_BLK;
        int add = (blk > 0) ? g_bsum[blk - 1] : 0;
        g_off[i + 1] = g_scan[i] + add;
        g_cur[i] = 0;
        if (i == 0) g_off[0] = 0;
        g_dinv[i] = rsqrtf((float)g_ideg[i] + 1.0f);
    }
    if (i < 2 * C) g_stats[i] = 0.0f;
}

__global__ void k_fill(const void* __restrict__ ei) {
    int e = blockIdx.x * blockDim.x + threadIdx.x;
    if (e >= EDGES) return;
    int src = load_idx(ei, e);
    int dst = load_idx(ei, (long long)EDGES + e);
    if ((unsigned)src >= NODES || (unsigned)dst >= NODES) return;
    int pos = g_off[dst] + atomicAdd(&g_cur[dst], 1);
    g_esrc[pos] = src;
    g_enorm[pos] = g_dinv[src] * g_dinv[dst];
}

// ---------------- mma.sync GEMM: 512 threads, warp tile 32x16, spill-free ---------
__global__ void __launch_bounds__(512, 1) k_gemm_mma(const float* __restrict__ x,
                                                     int use_x,
                                                     const float* __restrict__ W) {
    extern __shared__ __align__(16) uint32_t sw[];
    const int tid = threadIdx.x;
    const int wid = tid >> 5;
    const int lane = tid & 31;
    const int g = lane >> 2;
    const int tc = lane & 3;
    const int wm = wid & 1;       // row half (32 rows)
    const int wn = wid >> 1;      // col group of 16 (0..7)

    // ---- stage W^T hi/lo once: thread owns outcol n = tid&127, k-quarter tid>>7 ----
    {
        const int n = tid & 127;
        const int kq = tid >> 7;   // 0..3
#pragma unroll 4
        for (int k2 = 0; k2 < 16; k2++) {
            const int k = kq * 32 + k2 * 2;
            float w0 = __ldg(W + (size_t)k * C + n);
            float w1 = __ldg(W + (size_t)(k + 1) * C + n);
            uint32_t hp, lp;
            split2(w0, w1, hp, lp);
            const int kw = kq * 16 + k2;
            sw[WS_HI + n * ROWW + kw] = hp;
            sw[WS_LO + n * ROWW + kw] = lp;
        }
    }

    const float* __restrict__ hsrc = use_x ? x : (const float*)g_agg;
    const int row0 = tid >> 5;      // + it*16
    const int q4 = tid & 31;

    float4 sc4, sh4;
    if (!use_x) {
        sc4 = ((const float4*)g_ss)[q4];
        sh4 = ((const float4*)g_ss)[32 + q4];
    } else {
        sc4 = make_float4(1.f, 1.f, 1.f, 1.f);
        sh4 = make_float4(0.f, 0.f, 0.f, 0.f);
    }

    // ---- prefetch first tile's A into registers (4 float4/thread) ----
    float4 pf[4];
    int tile = blockIdx.x;
    {
        const int base = tile * MTILE;
        const int rem = (tile < NTILES) ? min(MTILE, NODES - base) : 0;
#pragma unroll
        for (int it = 0; it < 4; it++) {
            const int row = it * 16 + row0;
            pf[it] = (row < rem)
                ? __ldg((const float4*)(hsrc + (size_t)(base + row) * C) + q4)
                : make_float4(0.f, 0.f, 0.f, 0.f);
        }
    }

    for (; tile < NTILES; tile += gridDim.x) {
        const int base = tile * MTILE;
        const int rem = min(MTILE, NODES - base);

        __syncthreads();  // previous mainloop's LDS reads complete

        // ---- split + STS from prefetched registers (BN+ReLU fused) ----
#pragma unroll
        for (int it = 0; it < 4; it++) {
            float4 v = pf[it];
            if (!use_x) {
                v.x = fmaxf(fmaf(v.x, sc4.x, sh4.x), 0.f);
                v.y = fmaxf(fmaf(v.y, sc4.y, sh4.y), 0.f);
                v.z = fmaxf(fmaf(v.z, sc4.z, sh4.z), 0.f);
                v.w = fmaxf(fmaf(v.w, sc4.w, sh4.w), 0.f);
            }
            uint32_t h0, l0, h1, l1;
            split2(v.x, v.y, h0, l0);
            split2(v.z, v.w, h1, l1);
            const int p = (it * 16 + row0) * ROWW + q4 * 2;
            sw[AS_HI + p] = h0;  sw[AS_HI + p + 1] = h1;
            sw[AS_LO + p] = l0;  sw[AS_LO + p + 1] = l1;
        }
        __syncthreads();

        // ---- issue next tile's prefetch (overlaps with mainloop below) ----
        const int ntile = tile + gridDim.x;
        if (ntile < NTILES) {
            const int nbase = ntile * MTILE;
            const int nrem = min(MTILE, NODES - nbase);
#pragma unroll
            for (int it = 0; it < 4; it++) {
                const int row = it * 16 + row0;
                pf[it] = (row < nrem)
                    ? __ldg((const float4*)(hsrc + (size_t)(nbase + row) * C) + q4)
                    : make_float4(0.f, 0.f, 0.f, 0.f);
            }
        }

        // ---- mainloop: 8 k16-steps, warp tile 32x16 = 2m x 2n frags ----
        float acc[2][2][4];
#pragma unroll
        for (int mf = 0; mf < 2; mf++)
#pragma unroll
            for (int nf = 0; nf < 2; nf++)
#pragma unroll
                for (int j = 0; j < 4; j++) acc[mf][nf][j] = 0.f;

#pragma unroll
        for (int ks = 0; ks < 8; ks++) {
            uint32_t ah[2][4], al[2][4], bh[2][2], bl[2][2];
            const int cb = ks * 8 + tc;
#pragma unroll
            for (int mf = 0; mf < 2; mf++) {
                const int r = wm * 32 + mf * 16 + g;
                ah[mf][0] = sw[AS_HI + r * ROWW + cb];
                ah[mf][1] = sw[AS_HI + (r + 8) * ROWW + cb];
                ah[mf][2] = sw[AS_HI + r * ROWW + cb + 4];
                ah[mf][3] = sw[AS_HI + (r + 8) * ROWW + cb + 4];
                al[mf][0] = sw[AS_LO + r * ROWW + cb];
                al[mf][1] = sw[AS_LO + (r + 8) * ROWW + cb];
                al[mf][2] = sw[AS_LO + r * ROWW + cb + 4];
                al[mf][3] = sw[AS_LO + (r + 8) * ROWW + cb + 4];
            }
#pragma unroll
            for (int nf = 0; nf < 2; nf++) {
                const int n = wn * 16 + nf * 8 + g;
                bh[nf][0] = sw[WS_HI + n * ROWW + cb];
                bh[nf][1] = sw[WS_HI + n * ROWW + cb + 4];
                bl[nf][0] = sw[WS_LO + n * ROWW + cb];
                bl[nf][1] = sw[WS_LO + n * ROWW + cb + 4];
            }
#pragma unroll
            for (int mf = 0; mf < 2; mf++)
#pragma unroll
                for (int nf = 0; nf < 2; nf++) {
                    mma_bf16(acc[mf][nf], ah[mf], bh[nf]);
                    mma_bf16(acc[mf][nf], ah[mf], bl[nf]);
                    mma_bf16(acc[mf][nf], al[mf], bh[nf]);
                }
        }

        // ---- epilogue: fp16 output ----
#pragma unroll
        for (int mf = 0; mf < 2; mf++) {
            const int m0 = wm * 32 + mf * 16 + g;
#pragma unroll
            for (int nf = 0; nf < 2; nf++) {
                const int cc = wn * 16 + nf * 8 + tc * 2;
                if (m0 < rem) {
                    half2 p = __floats2half2_rn(acc[mf][nf][0], acc[mf][nf][1]);
                    *(half2*)(g_hw16 + (size_t)(base + m0) * C + cc) = p;
                }
                if (m0 + 8 < rem) {
                    half2 p = __floats2half2_rn(acc[mf][nf][2], acc[mf][nf][3]);
                    *(half2*)(g_hw16 + (size_t)(base + m0 + 8) * C + cc) = p;
                }
            }
        }
    }
}

// ------ gather aggregate + self-loop + bias + BN stats + last-block BN finalize ---
__global__ void __launch_bounds__(256) k_aggr(const float* __restrict__ b,
                                              const float* __restrict__ gamma,
                                              const float* __restrict__ beta) {
    __shared__ float sm[2 * C];
    __shared__ bool isLast;
    if (threadIdx.x < 2 * C) sm[threadIdx.x] = 0.f;
    __syncthreads();

    const int warp = threadIdx.x >> 5;
    const int lane = threadIdx.x & 31;
    const float4 bb = __ldg((const float4*)b + lane);

    float4 ts = make_float4(0.f, 0.f, 0.f, 0.f);
    float4 ts2 = make_float4(0.f, 0.f, 0.f, 0.f);

    for (int d = blockIdx.x * 8 + warp; d < NODES; d += gridDim.x * 8) {
        const int beg = g_off[d], end = g_off[d + 1];
        float s = g_dinv[d];
        s *= s;
        float4 acc = ld_row16(g_hw16 + (size_t)d * C, lane);
        acc.x = fmaf(acc.x, s, bb.x);
        acc.y = fmaf(acc.y, s, bb.y);
        acc.z = fmaf(acc.z, s, bb.z);
        acc.w = fmaf(acc.w, s, bb.w);

        int e = beg;
        for (; e + 4 <= end; e += 4) {
            const int s0 = g_esrc[e], s1 = g_esrc[e + 1], s2 = g_esrc[e + 2], s3 = g_esrc[e + 3];
            const float n0 = g_enorm[e], n1 = g_enorm[e + 1], n2 = g_enorm[e + 2], n3 = g_enorm[e + 3];
            const float4 v0 = ld_row16(g_hw16 + (size_t)s0 * C, lane);
            const float4 v1 = ld_row16(g_hw16 + (size_t)s1 * C, lane);
            const float4 v2 = ld_row16(g_hw16 + (size_t)s2 * C, lane);
            const float4 v3 = ld_row16(g_hw16 + (size_t)s3 * C, lane);
            acc.x = fmaf(v0.x, n0, acc.x); acc.y = fmaf(v0.y, n0, acc.y);
            acc.z = fmaf(v0.z, n0, acc.z); acc.w = fmaf(v0.w, n0, acc.w);
            acc.x = fmaf(v1.x, n1, acc.x); acc.y = fmaf(v1.y, n1, acc.y);
            acc.z = fmaf(v1.z, n1, acc.z); acc.w = fmaf(v1.w, n1, acc.w);
            acc.x = fmaf(v2.x, n2, acc.x); acc.y = fmaf(v2.y, n2, acc.y);
            acc.z = fmaf(v2.z, n2, acc.z); acc.w = fmaf(v2.w, n2, acc.w);
            acc.x = fmaf(v3.x, n3, acc.x); acc.y = fmaf(v3.y, n3, acc.y);
            acc.z = fmaf(v3.z, n3, acc.z); acc.w = fmaf(v3.w, n3, acc.w);
        }
        for (; e < end; e++) {
            const int s0 = g_esrc[e];
            const float n0 = g_enorm[e];
            const float4 v0 = ld_row16(g_hw16 + (size_t)s0 * C, lane);
            acc.x = fmaf(v0.x, n0, acc.x); acc.y = fmaf(v0.y, n0, acc.y);
            acc.z = fmaf(v0.z, n0, acc.z); acc.w = fmaf(v0.w, n0, acc.w);
        }

        *((float4*)(g_agg + (size_t)d * C) + lane) = acc;

        ts.x += acc.x; ts.y += acc.y; ts.z += acc.z; ts.w += acc.w;
        ts2.x = fmaf(acc.x, acc.x, ts2.x); ts2.y = fmaf(acc.y, acc.y, ts2.y);
        ts2.z = fmaf(acc.z, acc.z, ts2.z); ts2.w = fmaf(acc.w, acc.w, ts2.w);
    }

    const int c0 = lane * 4;
    atomicAdd(&sm[c0 + 0], ts.x);  atomicAdd(&sm[c0 + 1], ts.y);
    atomicAdd(&sm[c0 + 2], ts.z);  atomicAdd(&sm[c0 + 3], ts.w);
    atomicAdd(&sm[C + c0 + 0], ts2.x);  atomicAdd(&sm[C + c0 + 1], ts2.y);
    atomicAdd(&sm[C + c0 + 2], ts2.z);  atomicAdd(&sm[C + c0 + 3], ts2.w);
    __syncthreads();
    if (threadIdx.x < 2 * C) atomicAdd(&g_stats[threadIdx.x], sm[threadIdx.x]);

    if (threadIdx.x == 0) {
        __threadfence();
        int t = atomicAdd(&g_done, 1);
        isLast = (t == gridDim.x - 1);
    }
    __syncthreads();
    if (isLast) {
        int c = threadIdx.x;
        if (c < C) {
            const float inv_n = 1.0f / (float)NODES;
            float mean = __ldcg(&g_stats[c]) * inv_n;
            float var = __ldcg(&g_stats[C + c]) * inv_n - mean * mean;
            float sc = __ldg(gamma + c) * rsqrtf(var + BN_EPS);
            g_ss[c] = sc;
            g_ss[C + c] = fmaf(-mean, sc, __ldg(beta + c));
            g_stats[c] = 0.f;
            g_stats[C + c] = 0.f;
        }
        if (threadIdx.x == 255) g_done = 0;
    }
}

// ---------------- final normalize + ReLU -> d_out --------------------------------
__global__ void k_norm(float* __restrict__ dout) {
    int i = blockIdx.x * blockDim.x + threadIdx.x;
    if (i >= NODES * 32) return;
    int q = i & 31;
    float4 v = *((const float4*)g_agg + i);
    float4 sc = *((const float4*)g_ss + q);
    float4 sh = *((const float4*)(g_ss + C) + q);
    v.x = fmaxf(fmaf(v.x, sc.x, sh.x), 0.f);
    v.y = fmaxf(fmaf(v.y, sc.y, sh.y), 0.f);
    v.z = fmaxf(fmaf(v.z, sc.z, sh.z), 0.f);
    v.w = fmaxf(fmaf(v.w, sc.w, sh.w), 0.f);
    *((float4*)dout + i) = v;
}

// ---------------- launch -----------------------------------------------------------
extern "C" void kernel_launch(void* const* d_in, const int* in_sizes, int n_in,
                              void* d_out, int out_size) {
    const float* x = (const float*)d_in[0];
    const void* ei = d_in[1];
    const float* W[3]  = {(const float*)d_in[2],  (const float*)d_in[6],  (const float*)d_in[10]};
    const float* b[3]  = {(const float*)d_in[3],  (const float*)d_in[7],  (const float*)d_in[11]};
    const float* gm[3] = {(const float*)d_in[4],  (const float*)d_in[8],  (const float*)d_in[12]};
    const float* bt[3] = {(const float*)d_in[5],  (const float*)d_in[9],  (const float*)d_in[13]};

    static cudaStream_t s2 = 0;
    static cudaEvent_t evFork = 0, evJoin = 0;
    if (!s2) {
        cudaStreamCreateWithFlags(&s2, cudaStreamNonBlocking);
        cudaEventCreateWithFlags(&evFork, cudaEventDisableTiming);
        cudaEventCreateWithFlags(&evJoin, cudaEventDisableTiming);
        cudaFuncSetAttribute(k_gemm_mma, cudaFuncAttributeMaxDynamicSharedMemorySize,
                             SMEM_WORDS * 4);
    }

    const int vblk = (NODES * 32 + 255) / 256;

    // fork: CSR build on s2, concurrent with layer-0 GEMM.
    // k_gemm_mma is deliberately the 4th submitted launch so ncu's sampler
    // (which has been landing on launch #4) profiles the GEMM.
    cudaEventRecord(evFork, 0);
    cudaStreamWaitEvent(s2, evFork, 0);
    k_detect<<<(NODES + 255) / 256, 256, 0, s2>>>((const int*)ei);   // 1
    k_deg<<<(EDGES + 255) / 256, 256, 0, s2>>>(ei);                  // 2
    k_scan1<<<NBLK1, SCAN_BLK, 0, s2>>>();                           // 3
    k_gemm_mma<<<GEMM_BLOCKS, 512, SMEM_WORDS * 4>>>(x, 1, W[0]);    // 4 (main)
    k_scan2<<<1, 256, 0, s2>>>();                                    // 5
    k_scan3<<<(NODES + 255) / 256, 256, 0, s2>>>();                  // 6
    k_fill<<<(EDGES + 255) / 256, 256, 0, s2>>>(ei);                 // 7
    cudaEventRecord(evJoin, s2);
    cudaStreamWaitEvent(0, evJoin, 0);

    for (int L = 0; L < 3; L++) {
        if (L > 0) k_gemm_mma<<<GEMM_BLOCKS, 512, SMEM_WORDS * 4>>>(x, 0, W[L]);
        k_aggr<<<AGGR_BLOCKS, 256>>>(b[L], gm[L], bt[L]);
    }
    k_norm<<<vblk, 256>>>((float*)d_out);
}